// round 1
// baseline (speedup 1.0000x reference)
#include <cuda_runtime.h>
#include <math.h>

// Problem constants (fixed by reference)
#define BATCH   2
#define SEQ     2048
#define DMODEL  1024
#define NHEAD   16
#define DKH     64
#define DFF     4096
#define NROWS   (BATCH * SEQ)   // 4096

// ---------------------------------------------------------------------------
// Scratch (no cudaMalloc allowed anywhere)
// ---------------------------------------------------------------------------
__device__ float g_xn[NROWS * DMODEL];   // LN output (reused for LN1 and LN2)
__device__ float g_q [NROWS * DMODEL];
__device__ float g_k [NROWS * DMODEL];
__device__ float g_v [NROWS * DMODEL];
__device__ float g_at[NROWS * DMODEL];   // attention output (heads merged)
__device__ float g_h [NROWS * DMODEL];   // residual 1
__device__ float g_ff[NROWS * DFF];      // FFN hidden

// ---------------------------------------------------------------------------
// LayerNorm: one block per row of 1024, 256 threads x 4 elems
// ---------------------------------------------------------------------------
__global__ __launch_bounds__(256) void ln_kernel(
    const float* __restrict__ X, const float* __restrict__ gamma,
    const float* __restrict__ beta, float* __restrict__ Y)
{
    int row = blockIdx.x;
    int t   = threadIdx.x;
    const float4* x4 = (const float4*)(X + (size_t)row * DMODEL);
    float4 xv = x4[t];
    float s = xv.x + xv.y + xv.z + xv.w;
    float q = xv.x * xv.x + xv.y * xv.y + xv.z * xv.z + xv.w * xv.w;

#pragma unroll
    for (int off = 16; off > 0; off >>= 1) {
        s += __shfl_xor_sync(0xffffffffu, s, off);
        q += __shfl_xor_sync(0xffffffffu, q, off);
    }
    __shared__ float ss[8], sq[8];
    if ((t & 31) == 0) { ss[t >> 5] = s; sq[t >> 5] = q; }
    __syncthreads();
    __shared__ float smu, srstd;
    if (t == 0) {
        float S = 0.f, Q = 0.f;
#pragma unroll
        for (int i = 0; i < 8; i++) { S += ss[i]; Q += sq[i]; }
        float mu  = S * (1.0f / DMODEL);
        float var = Q * (1.0f / DMODEL) - mu * mu;
        smu   = mu;
        srstd = rsqrtf(var + 1e-5f);
    }
    __syncthreads();
    float mu = smu, r = srstd;
    float4 g4 = ((const float4*)gamma)[t];
    float4 b4 = ((const float4*)beta)[t];
    float4 y;
    y.x = (xv.x - mu) * r * g4.x + b4.x;
    y.y = (xv.y - mu) * r * g4.y + b4.y;
    y.z = (xv.z - mu) * r * g4.z + b4.z;
    y.w = (xv.w - mu) * r * g4.w + b4.w;
    ((float4*)(Y + (size_t)row * DMODEL))[t] = y;
}

// ---------------------------------------------------------------------------
// SGEMM: C[M,N] = A[M,K] @ B[K,N] + bias[N]  (+res[M,N]) (+relu)
// 128x128 block tile, BK=16, 256 threads, 8x8 microtile
// ---------------------------------------------------------------------------
#define BM 128
#define BN 128
#define BK 16
__global__ __launch_bounds__(256) void sgemm_kernel(
    const float* __restrict__ A, const float* __restrict__ B,
    const float* __restrict__ bias, const float* __restrict__ res,
    float* __restrict__ C, int M, int N, int K, int relu)
{
    __shared__ float As[BK][BM + 4];
    __shared__ float Bs[BK][BN];

    int bx  = blockIdx.x;           // N tile
    int by  = blockIdx.y;           // M tile
    int tid = threadIdx.x;
    int tcol = tid & 15;            // 0..15
    int trow = tid >> 4;            // 0..15

    const float* Aptr = A + (size_t)by * BM * K;
    const float* Bptr = B + (size_t)bx * BN;

    // A tile loads: 128x16, 2 float4 per thread
    int aRow = tid >> 2;            // 0..63
    int aCol = (tid & 3) * 4;       // 0,4,8,12
    // B tile loads: 16x128, 2 float4 per thread
    int bRow = tid >> 5;            // 0..7
    int bCol = (tid & 31) * 4;      // 0..124

    float acc[8][8];
#pragma unroll
    for (int i = 0; i < 8; i++)
#pragma unroll
        for (int j = 0; j < 8; j++) acc[i][j] = 0.f;

    for (int k0 = 0; k0 < K; k0 += BK) {
        float4 a0 = *(const float4*)(Aptr + (size_t)aRow        * K + k0 + aCol);
        float4 a1 = *(const float4*)(Aptr + (size_t)(aRow + 64) * K + k0 + aCol);
        As[aCol + 0][aRow]      = a0.x;
        As[aCol + 1][aRow]      = a0.y;
        As[aCol + 2][aRow]      = a0.z;
        As[aCol + 3][aRow]      = a0.w;
        As[aCol + 0][aRow + 64] = a1.x;
        As[aCol + 1][aRow + 64] = a1.y;
        As[aCol + 2][aRow + 64] = a1.z;
        As[aCol + 3][aRow + 64] = a1.w;
        float4 b0 = *(const float4*)(Bptr + (size_t)(k0 + bRow)     * N + bCol);
        float4 b1 = *(const float4*)(Bptr + (size_t)(k0 + bRow + 8) * N + bCol);
        *(float4*)&Bs[bRow][bCol]     = b0;
        *(float4*)&Bs[bRow + 8][bCol] = b1;
        __syncthreads();

#pragma unroll
        for (int kk = 0; kk < BK; ++kk) {
            float ra[8], rb[8];
            float4 ra0 = *(const float4*)&As[kk][trow * 8];
            float4 ra1 = *(const float4*)&As[kk][trow * 8 + 4];
            float4 rb0 = *(const float4*)&Bs[kk][tcol * 8];
            float4 rb1 = *(const float4*)&Bs[kk][tcol * 8 + 4];
            ra[0] = ra0.x; ra[1] = ra0.y; ra[2] = ra0.z; ra[3] = ra0.w;
            ra[4] = ra1.x; ra[5] = ra1.y; ra[6] = ra1.z; ra[7] = ra1.w;
            rb[0] = rb0.x; rb[1] = rb0.y; rb[2] = rb0.z; rb[3] = rb0.w;
            rb[4] = rb1.x; rb[5] = rb1.y; rb[6] = rb1.z; rb[7] = rb1.w;
#pragma unroll
            for (int i = 0; i < 8; i++)
#pragma unroll
                for (int j = 0; j < 8; j++)
                    acc[i][j] += ra[i] * rb[j];
        }
        __syncthreads();
    }

    // Epilogue
#pragma unroll
    for (int i = 0; i < 8; i++) {
        int r = by * BM + trow * 8 + i;
#pragma unroll
        for (int j4 = 0; j4 < 2; j4++) {
            int c = bx * BN + tcol * 8 + j4 * 4;
            float4 v;
            v.x = acc[i][j4 * 4 + 0];
            v.y = acc[i][j4 * 4 + 1];
            v.z = acc[i][j4 * 4 + 2];
            v.w = acc[i][j4 * 4 + 3];
            float4 bb = *(const float4*)(bias + c);
            v.x += bb.x; v.y += bb.y; v.z += bb.z; v.w += bb.w;
            if (relu) {
                v.x = fmaxf(v.x, 0.f); v.y = fmaxf(v.y, 0.f);
                v.z = fmaxf(v.z, 0.f); v.w = fmaxf(v.w, 0.f);
            }
            if (res) {
                float4 rr = *(const float4*)(res + (size_t)r * N + c);
                v.x += rr.x; v.y += rr.y; v.z += rr.z; v.w += rr.w;
            }
            *(float4*)(C + (size_t)r * N + c) = v;
        }
    }
}

// ---------------------------------------------------------------------------
// Flash attention (causal), fp32.
// Grid: (SEQ/128, BATCH*NHEAD). Block: 128 threads, 1 query row per thread.
// KV tiles of 32 keys. Q/K/V laid out [B*S, DMODEL] (head h at col h*64).
// ---------------------------------------------------------------------------
#define QROWS 128
#define KT    32
__global__ __launch_bounds__(128) void flash_attn_kernel(
    const float* __restrict__ Q, const float* __restrict__ Km,
    const float* __restrict__ Vm, float* __restrict__ O)
{
    __shared__ float Ks[KT][DKH + 4];
    __shared__ float Vs[KT][DKH + 4];
    __shared__ float Sc[QROWS][KT + 1];

    int t  = threadIdx.x;           // 0..127
    int bh = blockIdx.y;
    int b  = bh >> 4;
    int h  = bh & 15;
    int q0 = blockIdx.x * QROWS;
    int row = q0 + t;               // query position in sequence

    // Load this thread's q row into registers (16 float4 = 64 floats)
    float4 qr[16];
    const float4* qrow = (const float4*)(Q + ((size_t)(b * SEQ + row)) * DMODEL + h * DKH);
#pragma unroll
    for (int i = 0; i < 16; i++) qr[i] = qrow[i];

    float m = -1e30f, l = 0.f;
    float4 o[16];
#pragma unroll
    for (int i = 0; i < 16; i++) o[i] = make_float4(0.f, 0.f, 0.f, 0.f);

    int ntiles = (q0 + QROWS) / KT;
    int lc = t & 63;                // load col
    int lr0 = t >> 6;               // 0/1

    for (int jt = 0; jt < ntiles; ++jt) {
        int k0 = jt * KT;
        // cooperative K/V tile load (coalesced 64-float rows)
#pragma unroll
        for (int i = 0; i < 16; ++i) {
            int r = 2 * i + lr0;    // 0..31
            size_t gidx = ((size_t)(b * SEQ + k0 + r)) * DMODEL + h * DKH + lc;
            Ks[r][lc] = Km[gidx];
            Vs[r][lc] = Vm[gidx];
        }
        __syncthreads();

        // scores for my row vs this key tile
        float mt = -1e30f;
#pragma unroll 4
        for (int j = 0; j < KT; ++j) {
            float sx = 0.f, sy = 0.f, sz = 0.f, sw = 0.f;
#pragma unroll
            for (int d4 = 0; d4 < 16; ++d4) {
                float4 kv = *(const float4*)&Ks[j][d4 * 4];
                sx += qr[d4].x * kv.x;
                sy += qr[d4].y * kv.y;
                sz += qr[d4].z * kv.z;
                sw += qr[d4].w * kv.w;
            }
            float s = ((sx + sy) + (sz + sw)) * 0.125f;   // 1/sqrt(64)
            if (k0 + j > row) s = -1e9f;                  // causal
            mt = fmaxf(mt, s);
            Sc[t][j] = s;
        }

        float newm = fmaxf(m, mt);
        float corr = __expf(m - newm);
        l *= corr;
#pragma unroll
        for (int i = 0; i < 16; i++) {
            o[i].x *= corr; o[i].y *= corr; o[i].z *= corr; o[i].w *= corr;
        }
#pragma unroll 4
        for (int j = 0; j < KT; ++j) {
            float p = __expf(Sc[t][j] - newm);
            l += p;
#pragma unroll
            for (int d4 = 0; d4 < 16; ++d4) {
                float4 vv = *(const float4*)&Vs[j][d4 * 4];
                o[d4].x += p * vv.x;
                o[d4].y += p * vv.y;
                o[d4].z += p * vv.z;
                o[d4].w += p * vv.w;
            }
        }
        m = newm;
        __syncthreads();
    }

    float inv = 1.f / l;
    float4* orow = (float4*)(O + ((size_t)(b * SEQ + row)) * DMODEL + h * DKH);
#pragma unroll
    for (int i = 0; i < 16; i++) {
        float4 v = o[i];
        v.x *= inv; v.y *= inv; v.z *= inv; v.w *= inv;
        orow[i] = v;
    }
}

// ---------------------------------------------------------------------------
// Launcher
// ---------------------------------------------------------------------------
extern "C" void kernel_launch(void* const* d_in, const int* in_sizes, int n_in,
                              void* d_out, int out_size)
{
    const float* x   = (const float*)d_in[0];
    // d_in[1] = mask -> ignored; causality is hard-coded (reference uses tril mask)
    const float* Wq  = (const float*)d_in[2];
    const float* bq  = (const float*)d_in[3];
    const float* Wk  = (const float*)d_in[4];
    const float* bk  = (const float*)d_in[5];
    const float* Wv  = (const float*)d_in[6];
    const float* bv  = (const float*)d_in[7];
    const float* Wo  = (const float*)d_in[8];
    const float* bo  = (const float*)d_in[9];
    const float* W1  = (const float*)d_in[10];
    const float* b1  = (const float*)d_in[11];
    const float* W2  = (const float*)d_in[12];
    const float* b2  = (const float*)d_in[13];
    const float* g1  = (const float*)d_in[14];
    const float* be1 = (const float*)d_in[15];
    const float* g2  = (const float*)d_in[16];
    const float* be2 = (const float*)d_in[17];
    float* out = (float*)d_out;

    float *xn, *q, *k, *v, *at, *h, *ff;
    cudaGetSymbolAddress((void**)&xn, g_xn);
    cudaGetSymbolAddress((void**)&q,  g_q);
    cudaGetSymbolAddress((void**)&k,  g_k);
    cudaGetSymbolAddress((void**)&v,  g_v);
    cudaGetSymbolAddress((void**)&at, g_at);
    cudaGetSymbolAddress((void**)&h,  g_h);
    cudaGetSymbolAddress((void**)&ff, g_ff);

    // 1. LN1
    ln_kernel<<<NROWS, 256>>>(x, g1, be1, xn);

    // 2. QKV projections
    dim3 gQ(DMODEL / BN, NROWS / BM);
    sgemm_kernel<<<gQ, 256>>>(xn, Wq, bq, nullptr, q, NROWS, DMODEL, DMODEL, 0);
    sgemm_kernel<<<gQ, 256>>>(xn, Wk, bk, nullptr, k, NROWS, DMODEL, DMODEL, 0);
    sgemm_kernel<<<gQ, 256>>>(xn, Wv, bv, nullptr, v, NROWS, DMODEL, DMODEL, 0);

    // 3. Causal flash attention
    dim3 gA(SEQ / QROWS, BATCH * NHEAD);
    flash_attn_kernel<<<gA, 128>>>(q, k, v, at);

    // 4. Output projection + residual(x) -> h
    sgemm_kernel<<<gQ, 256>>>(at, Wo, bo, x, h, NROWS, DMODEL, DMODEL, 0);

    // 5. LN2 (reuse xn)
    ln_kernel<<<NROWS, 256>>>(h, g2, be2, xn);

    // 6. FFN1 + relu
    dim3 gF1(DFF / BN, NROWS / BM);
    sgemm_kernel<<<gF1, 256>>>(xn, W1, b1, nullptr, ff, NROWS, DFF, DMODEL, 1);

    // 7. FFN2 + residual(h) -> out
    dim3 gF2(DMODEL / BN, NROWS / BM);
    sgemm_kernel<<<gF2, 256>>>(ff, W2, b2, h, out, NROWS, DMODEL, DFF, 0);
}

// round 3
// speedup vs baseline: 1.6289x; 1.6289x over previous
#include <cuda_runtime.h>
#include <cuda_bf16.h>
#include <cstdint>
#include <math.h>

// Problem constants
#define BATCH   2
#define SEQ     2048
#define DMODEL  1024
#define NHEAD   16
#define DKH     64
#define DFF     4096
#define NROWS   (BATCH * SEQ)   // 4096

// ===========================================================================
// Helpers
// ===========================================================================
__device__ __forceinline__ uint32_t smem_to_u32(const void* p) {
    uint32_t a;
    asm("{ .reg .u64 t; cvta.to.shared.u64 t, %1; cvt.u32.u64 %0, t; }" : "=r"(a) : "l"(p));
    return a;
}
__device__ __forceinline__ void cp_async16(uint32_t s, const void* g) {
    asm volatile("cp.async.cg.shared.global [%0], [%1], 16;" :: "r"(s), "l"(g));
}
__device__ __forceinline__ void cp_commit() {
    asm volatile("cp.async.commit_group;" ::: "memory");
}
template <int N>
__device__ __forceinline__ void cp_wait() {
    asm volatile("cp.async.wait_group %0;" :: "n"(N) : "memory");
}
__device__ __forceinline__ void ldmx4(uint32_t* r, uint32_t addr) {
    asm volatile("ldmatrix.sync.aligned.m8n8.x4.shared.b16 {%0,%1,%2,%3}, [%4];"
                 : "=r"(r[0]), "=r"(r[1]), "=r"(r[2]), "=r"(r[3]) : "r"(addr));
}
__device__ __forceinline__ void mma16816(float* d, const uint32_t* a, const uint32_t* b) {
    asm volatile("mma.sync.aligned.m16n8k16.row.col.f32.bf16.bf16.f32 "
                 "{%0,%1,%2,%3}, {%4,%5,%6,%7}, {%8,%9}, {%0,%1,%2,%3};"
                 : "+f"(d[0]), "+f"(d[1]), "+f"(d[2]), "+f"(d[3])
                 : "r"(a[0]), "r"(a[1]), "r"(a[2]), "r"(a[3]), "r"(b[0]), "r"(b[1]));
}
__device__ __forceinline__ void split2(float v, __nv_bfloat16& h, __nv_bfloat16& l) {
    h = __float2bfloat16(v);
    l = __float2bfloat16(v - __bfloat162float(h));
}

// ===========================================================================
// Scratch (__device__ globals; no cudaMalloc allowed)
// ===========================================================================
__device__ __nv_bfloat16 g_xnh[NROWS * DMODEL], g_xnl[NROWS * DMODEL];
__device__ __nv_bfloat16 g_ath[NROWS * DMODEL], g_atl[NROWS * DMODEL];
__device__ __nv_bfloat16 g_ffh[NROWS * DFF],    g_ffl[NROWS * DFF];
__device__ __nv_bfloat16 g_wqh[DMODEL * DMODEL], g_wql[DMODEL * DMODEL];
__device__ __nv_bfloat16 g_wkh[DMODEL * DMODEL], g_wkl[DMODEL * DMODEL];
__device__ __nv_bfloat16 g_wvh[DMODEL * DMODEL], g_wvl[DMODEL * DMODEL];
__device__ __nv_bfloat16 g_woh[DMODEL * DMODEL], g_wol[DMODEL * DMODEL];
__device__ __nv_bfloat16 g_w1h[DFF * DMODEL],    g_w1l[DFF * DMODEL];
__device__ __nv_bfloat16 g_w2h[DMODEL * DFF],    g_w2l[DMODEL * DFF];
__device__ float g_q[NROWS * DMODEL], g_k[NROWS * DMODEL], g_v[NROWS * DMODEL];
__device__ float g_h[NROWS * DMODEL];

// ===========================================================================
// Weight transpose + bf16 split: W[K,N] fp32 -> Th/Tl[N,K] bf16
// ===========================================================================
__global__ __launch_bounds__(256) void transpose_split_kernel(
    const float* __restrict__ W, __nv_bfloat16* __restrict__ Th,
    __nv_bfloat16* __restrict__ Tl, int K, int N)
{
    __shared__ float tile[32][33];
    int n0 = blockIdx.x * 32, k0 = blockIdx.y * 32;
    int tx = threadIdx.x & 31, ty = threadIdx.x >> 5;   // 32 x 8
#pragma unroll
    for (int i = 0; i < 4; i++)
        tile[ty + i * 8][tx] = W[(size_t)(k0 + ty + i * 8) * N + n0 + tx];
    __syncthreads();
#pragma unroll
    for (int i = 0; i < 4; i++) {
        float v = tile[tx][ty + i * 8];
        __nv_bfloat16 h, l;
        split2(v, h, l);
        size_t o = (size_t)(n0 + ty + i * 8) * K + k0 + tx;
        Th[o] = h; Tl[o] = l;
    }
}

// ===========================================================================
// LayerNorm (split bf16 output): one block per row, 256 threads x 4 elems
// ===========================================================================
__global__ __launch_bounds__(256) void ln_kernel(
    const float* __restrict__ X, const float* __restrict__ gamma,
    const float* __restrict__ beta, __nv_bfloat16* __restrict__ Yh,
    __nv_bfloat16* __restrict__ Yl)
{
    int row = blockIdx.x;
    int t   = threadIdx.x;
    float4 xv = ((const float4*)(X + (size_t)row * DMODEL))[t];
    float s = xv.x + xv.y + xv.z + xv.w;
    float q = xv.x * xv.x + xv.y * xv.y + xv.z * xv.z + xv.w * xv.w;
#pragma unroll
    for (int off = 16; off > 0; off >>= 1) {
        s += __shfl_xor_sync(0xffffffffu, s, off);
        q += __shfl_xor_sync(0xffffffffu, q, off);
    }
    __shared__ float ss[8], sq[8];
    if ((t & 31) == 0) { ss[t >> 5] = s; sq[t >> 5] = q; }
    __syncthreads();
    __shared__ float smu, srstd;
    if (t == 0) {
        float S = 0.f, Q = 0.f;
#pragma unroll
        for (int i = 0; i < 8; i++) { S += ss[i]; Q += sq[i]; }
        float mu  = S * (1.0f / DMODEL);
        float var = Q * (1.0f / DMODEL) - mu * mu;
        smu = mu; srstd = rsqrtf(var + 1e-5f);
    }
    __syncthreads();
    float mu = smu, r = srstd;
    float4 g4 = ((const float4*)gamma)[t];
    float4 b4 = ((const float4*)beta)[t];
    float y[4];
    y[0] = (xv.x - mu) * r * g4.x + b4.x;
    y[1] = (xv.y - mu) * r * g4.y + b4.y;
    y[2] = (xv.z - mu) * r * g4.z + b4.z;
    y[3] = (xv.w - mu) * r * g4.w + b4.w;
    __nv_bfloat16 h[4], l[4];
#pragma unroll
    for (int i = 0; i < 4; i++) split2(y[i], h[i], l[i]);
    size_t base = (size_t)row * DMODEL + t * 4;
    *(__nv_bfloat162*)(Yh + base)     = __halves2bfloat162(h[0], h[1]);
    *(__nv_bfloat162*)(Yh + base + 2) = __halves2bfloat162(h[2], h[3]);
    *(__nv_bfloat162*)(Yl + base)     = __halves2bfloat162(l[0], l[1]);
    *(__nv_bfloat162*)(Yl + base + 2) = __halves2bfloat162(l[2], l[3]);
}

// ===========================================================================
// HMMA bf16-split GEMM: C[M,N] = A @ Bt^T + bias (+res | relu+split-out)
// A: Ah/Al [M,K] bf16. B: Bh/Bl [N,K] bf16 (pre-transposed).
// 128x128 CTA tile, 8 warps (2x4), warp tile 64x32. K chunk 32, 2-stage
// cp.async double buffer. 3-term split: Ah*Bh + Al*Bh + Ah*Bl (fp32 acc).
// modes: 0 = fp32 out (+bias), 1 = +bias+res, 2 = bf16-split out (+bias, relu)
// ===========================================================================
#define BKC 32
#define TSTRIDE 80                     // smem bytes per row (pad kills conflicts)
#define TBYTES (128 * TSTRIDE)         // 10240 per tile
#define STG_BYTES (4 * TBYTES)         // Ah, Al, Bh, Bl
#define HSMEM_TOTAL (2 * STG_BYTES)    // 81920

__device__ __forceinline__ void load_stage(
    const __nv_bfloat16* __restrict__ Ah, const __nv_bfloat16* __restrict__ Al,
    const __nv_bfloat16* __restrict__ Bh, const __nv_bfloat16* __restrict__ Bl,
    int m0, int n0, int k0, int K, uint32_t sbase)
{
    int tid = threadIdx.x;
    const __nv_bfloat16* gt[4] = {
        Ah + (size_t)m0 * K, Al + (size_t)m0 * K,
        Bh + (size_t)n0 * K, Bl + (size_t)n0 * K };
#pragma unroll
    for (int T = 0; T < 4; T++) {
#pragma unroll
        for (int j = 0; j < 2; j++) {
            int e = tid + j * 256;          // 0..511
            int row = e >> 2, s = e & 3;
            const void* g = (const char*)(gt[T] + (size_t)row * K + k0) + s * 16;
            cp_async16(sbase + T * TBYTES + row * TSTRIDE + s * 16, g);
        }
    }
}

__global__ __launch_bounds__(256, 1) void gemm_hmma_kernel(
    const __nv_bfloat16* __restrict__ Ah, const __nv_bfloat16* __restrict__ Al,
    const __nv_bfloat16* __restrict__ Bh, const __nv_bfloat16* __restrict__ Bl,
    const float* __restrict__ bias, const float* __restrict__ res,
    float* __restrict__ outF, __nv_bfloat16* __restrict__ outBh,
    __nv_bfloat16* __restrict__ outBl, int N, int K, int mode)
{
    extern __shared__ char smem[];
    uint32_t sb = smem_to_u32(smem);
    int tid = threadIdx.x, wid = tid >> 5, lane = tid & 31;
    int m0 = blockIdx.y * 128, n0 = blockIdx.x * 128;
    int wy = wid >> 2, wx = wid & 3;     // warp tile origin: (wy*64, wx*32)

    float acc[4][4][4];
#pragma unroll
    for (int a = 0; a < 4; a++)
#pragma unroll
        for (int b = 0; b < 4; b++)
#pragma unroll
            for (int c = 0; c < 4; c++) acc[a][b][c] = 0.f;

    const int NC = K >> 5;

    load_stage(Ah, Al, Bh, Bl, m0, n0, 0, K, sb);
    cp_commit();

    // ldmatrix address components (constant per thread)
    int arow = (lane & 7) + ((lane >> 3) & 1) * 8;   // A: row-in-16 block
    int akof = (lane >> 4) * 16;                      // A: k quadrant byte off
    int brow = (lane & 7) + (lane >> 4) * 8;          // B: n row within 16
    int bkof = ((lane >> 3) & 1) * 16;                // B: k quadrant byte off

    for (int i = 0; i < NC; i++) {
        int s = i & 1;
        if (i + 1 < NC) {
            load_stage(Ah, Al, Bh, Bl, m0, n0, (i + 1) * BKC, K, sb + (s ^ 1) * STG_BYTES);
            cp_commit();
            cp_wait<1>();
        } else {
            cp_wait<0>();
        }
        __syncthreads();

        uint32_t st = sb + s * STG_BYTES;
#pragma unroll
        for (int kh = 0; kh < 2; kh++) {
            uint32_t Afh[4][4], Afl[4][4];
            uint32_t Bfh[4][2], Bfl[4][2];
#pragma unroll
            for (int mt = 0; mt < 4; mt++) {
                uint32_t addr = st + (wy * 64 + mt * 16 + arow) * TSTRIDE + kh * 32 + akof;
                ldmx4(Afh[mt], addr);
                ldmx4(Afl[mt], addr + TBYTES);
            }
#pragma unroll
            for (int ntp = 0; ntp < 2; ntp++) {
                uint32_t addr = st + 2 * TBYTES +
                                (wx * 32 + ntp * 16 + brow) * TSTRIDE + kh * 32 + bkof;
                uint32_t r[4];
                ldmx4(r, addr);
                Bfh[ntp * 2][0] = r[0]; Bfh[ntp * 2][1] = r[1];
                Bfh[ntp * 2 + 1][0] = r[2]; Bfh[ntp * 2 + 1][1] = r[3];
                ldmx4(r, addr + TBYTES);
                Bfl[ntp * 2][0] = r[0]; Bfl[ntp * 2][1] = r[1];
                Bfl[ntp * 2 + 1][0] = r[2]; Bfl[ntp * 2 + 1][1] = r[3];
            }
#pragma unroll
            for (int mt = 0; mt < 4; mt++)
#pragma unroll
                for (int nt = 0; nt < 4; nt++) {
                    mma16816(acc[mt][nt], Afh[mt], Bfh[nt]);
                    mma16816(acc[mt][nt], Afl[mt], Bfh[nt]);
                    mma16816(acc[mt][nt], Afh[mt], Bfl[nt]);
                }
        }
        __syncthreads();
    }

    // Epilogue
#pragma unroll
    for (int mt = 0; mt < 4; mt++) {
#pragma unroll
        for (int nt = 0; nt < 4; nt++) {
            int r0 = m0 + wy * 64 + mt * 16 + (lane >> 2);
            int c  = n0 + wx * 32 + nt * 8 + (lane & 3) * 2;
            float b0 = bias[c], b1 = bias[c + 1];
#pragma unroll
            for (int half = 0; half < 2; half++) {
                int r = r0 + half * 8;
                float v0 = acc[mt][nt][half * 2 + 0] + b0;
                float v1 = acc[mt][nt][half * 2 + 1] + b1;
                size_t o = (size_t)r * N + c;
                if (mode == 2) {
                    v0 = fmaxf(v0, 0.f); v1 = fmaxf(v1, 0.f);
                    __nv_bfloat16 h0, l0, h1, l1;
                    split2(v0, h0, l0); split2(v1, h1, l1);
                    *(__nv_bfloat162*)(outBh + o) = __halves2bfloat162(h0, h1);
                    *(__nv_bfloat162*)(outBl + o) = __halves2bfloat162(l0, l1);
                } else {
                    if (mode == 1) {
                        float2 rr = *(const float2*)(res + o);
                        v0 += rr.x; v1 += rr.y;
                    }
                    float2 w; w.x = v0; w.y = v1;
                    *(float2*)(outF + o) = w;
                }
            }
        }
    }
}

// ===========================================================================
// Flash attention (causal), fp32, split-bf16 output.
// Grid: (SEQ/128, BATCH*NHEAD). Block: 128 threads, 1 query row per thread.
// ===========================================================================
#define QROWS 128
#define KT    32
__global__ __launch_bounds__(128) void flash_attn_kernel(
    const float* __restrict__ Q, const float* __restrict__ Km,
    const float* __restrict__ Vm, __nv_bfloat16* __restrict__ Oh,
    __nv_bfloat16* __restrict__ Ol)
{
    __shared__ float Ks[KT][DKH + 4];
    __shared__ float Vs[KT][DKH + 4];
    __shared__ float Sc[QROWS][KT + 1];

    int t  = threadIdx.x;
    int bh = blockIdx.y;
    int b  = bh >> 4;
    int h  = bh & 15;
    int q0 = blockIdx.x * QROWS;
    int row = q0 + t;

    float4 qr[16];
    const float4* qrow = (const float4*)(Q + ((size_t)(b * SEQ + row)) * DMODEL + h * DKH);
#pragma unroll
    for (int i = 0; i < 16; i++) qr[i] = qrow[i];

    float m = -1e30f, l = 0.f;
    float4 o[16];
#pragma unroll
    for (int i = 0; i < 16; i++) o[i] = make_float4(0.f, 0.f, 0.f, 0.f);

    int ntiles = (q0 + QROWS) / KT;
    int lc = t & 63;
    int lr0 = t >> 6;

    for (int jt = 0; jt < ntiles; ++jt) {
        int k0 = jt * KT;
#pragma unroll
        for (int i = 0; i < 16; ++i) {
            int r = 2 * i + lr0;
            size_t gidx = ((size_t)(b * SEQ + k0 + r)) * DMODEL + h * DKH + lc;
            Ks[r][lc] = Km[gidx];
            Vs[r][lc] = Vm[gidx];
        }
        __syncthreads();

        float mt = -1e30f;
#pragma unroll 4
        for (int j = 0; j < KT; ++j) {
            float sx = 0.f, sy = 0.f, sz = 0.f, sw = 0.f;
#pragma unroll
            for (int d4 = 0; d4 < 16; ++d4) {
                float4 kv = *(const float4*)&Ks[j][d4 * 4];
                sx += qr[d4].x * kv.x;
                sy += qr[d4].y * kv.y;
                sz += qr[d4].z * kv.z;
                sw += qr[d4].w * kv.w;
            }
            float s = ((sx + sy) + (sz + sw)) * 0.125f;
            if (k0 + j > row) s = -1e9f;
            mt = fmaxf(mt, s);
            Sc[t][j] = s;
        }

        float newm = fmaxf(m, mt);
        float corr = __expf(m - newm);
        l *= corr;
#pragma unroll
        for (int i = 0; i < 16; i++) {
            o[i].x *= corr; o[i].y *= corr; o[i].z *= corr; o[i].w *= corr;
        }
#pragma unroll 4
        for (int j = 0; j < KT; ++j) {
            float p = __expf(Sc[t][j] - newm);
            l += p;
#pragma unroll
            for (int d4 = 0; d4 < 16; ++d4) {
                float4 vv = *(const float4*)&Vs[j][d4 * 4];
                o[d4].x += p * vv.x;
                o[d4].y += p * vv.y;
                o[d4].z += p * vv.z;
                o[d4].w += p * vv.w;
            }
        }
        m = newm;
        __syncthreads();
    }

    float inv = 1.f / l;
    size_t base = ((size_t)(b * SEQ + row)) * DMODEL + h * DKH;
#pragma unroll
    for (int i = 0; i < 16; i++) {
        float vv[4] = { o[i].x * inv, o[i].y * inv, o[i].z * inv, o[i].w * inv };
        __nv_bfloat16 hh[4], ll[4];
#pragma unroll
        for (int c = 0; c < 4; c++) split2(vv[c], hh[c], ll[c]);
        *(__nv_bfloat162*)(Oh + base + i * 4)     = __halves2bfloat162(hh[0], hh[1]);
        *(__nv_bfloat162*)(Oh + base + i * 4 + 2) = __halves2bfloat162(hh[2], hh[3]);
        *(__nv_bfloat162*)(Ol + base + i * 4)     = __halves2bfloat162(ll[0], ll[1]);
        *(__nv_bfloat162*)(Ol + base + i * 4 + 2) = __halves2bfloat162(ll[2], ll[3]);
    }
}

// ===========================================================================
// Launcher
// ===========================================================================
extern "C" void kernel_launch(void* const* d_in, const int* in_sizes, int n_in,
                              void* d_out, int out_size)
{
    const float* x   = (const float*)d_in[0];
    const float* Wq  = (const float*)d_in[2];
    const float* bq  = (const float*)d_in[3];
    const float* Wk  = (const float*)d_in[4];
    const float* bk  = (const float*)d_in[5];
    const float* Wv  = (const float*)d_in[6];
    const float* bv  = (const float*)d_in[7];
    const float* Wo  = (const float*)d_in[8];
    const float* bo  = (const float*)d_in[9];
    const float* W1  = (const float*)d_in[10];
    const float* b1  = (const float*)d_in[11];
    const float* W2  = (const float*)d_in[12];
    const float* b2  = (const float*)d_in[13];
    const float* g1  = (const float*)d_in[14];
    const float* be1 = (const float*)d_in[15];
    const float* g2  = (const float*)d_in[16];
    const float* be2 = (const float*)d_in[17];
    float* out = (float*)d_out;

    __nv_bfloat16 *xnh, *xnl, *ath, *atl, *ffh, *ffl;
    __nv_bfloat16 *wqh, *wql, *wkh, *wkl, *wvh, *wvl, *woh, *wol, *w1h, *w1l, *w2h, *w2l;
    float *q, *k, *v, *h;
    cudaGetSymbolAddress((void**)&xnh, g_xnh); cudaGetSymbolAddress((void**)&xnl, g_xnl);
    cudaGetSymbolAddress((void**)&ath, g_ath); cudaGetSymbolAddress((void**)&atl, g_atl);
    cudaGetSymbolAddress((void**)&ffh, g_ffh); cudaGetSymbolAddress((void**)&ffl, g_ffl);
    cudaGetSymbolAddress((void**)&wqh, g_wqh); cudaGetSymbolAddress((void**)&wql, g_wql);
    cudaGetSymbolAddress((void**)&wkh, g_wkh); cudaGetSymbolAddress((void**)&wkl, g_wkl);
    cudaGetSymbolAddress((void**)&wvh, g_wvh); cudaGetSymbolAddress((void**)&wvl, g_wvl);
    cudaGetSymbolAddress((void**)&woh, g_woh); cudaGetSymbolAddress((void**)&wol, g_wol);
    cudaGetSymbolAddress((void**)&w1h, g_w1h); cudaGetSymbolAddress((void**)&w1l, g_w1l);
    cudaGetSymbolAddress((void**)&w2h, g_w2h); cudaGetSymbolAddress((void**)&w2l, g_w2l);
    cudaGetSymbolAddress((void**)&q, g_q); cudaGetSymbolAddress((void**)&k, g_k);
    cudaGetSymbolAddress((void**)&v, g_v); cudaGetSymbolAddress((void**)&h, g_h);

    cudaFuncSetAttribute(gemm_hmma_kernel,
                         cudaFuncAttributeMaxDynamicSharedMemorySize, HSMEM_TOTAL);

    // Weight transpose + split
    dim3 tb(256);
    transpose_split_kernel<<<dim3(DMODEL / 32, DMODEL / 32), tb>>>(Wq, wqh, wql, DMODEL, DMODEL);
    transpose_split_kernel<<<dim3(DMODEL / 32, DMODEL / 32), tb>>>(Wk, wkh, wkl, DMODEL, DMODEL);
    transpose_split_kernel<<<dim3(DMODEL / 32, DMODEL / 32), tb>>>(Wv, wvh, wvl, DMODEL, DMODEL);
    transpose_split_kernel<<<dim3(DMODEL / 32, DMODEL / 32), tb>>>(Wo, woh, wol, DMODEL, DMODEL);
    transpose_split_kernel<<<dim3(DFF / 32, DMODEL / 32), tb>>>(W1, w1h, w1l, DMODEL, DFF);
    transpose_split_kernel<<<dim3(DMODEL / 32, DFF / 32), tb>>>(W2, w2h, w2l, DFF, DMODEL);

    // 1. LN1 -> split
    ln_kernel<<<NROWS, 256>>>(x, g1, be1, xnh, xnl);

    // 2. QKV projections (HMMA)
    dim3 gQ(DMODEL / 128, NROWS / 128);
    gemm_hmma_kernel<<<gQ, 256, HSMEM_TOTAL>>>(xnh, xnl, wqh, wql, bq, nullptr, q, nullptr, nullptr, DMODEL, DMODEL, 0);
    gemm_hmma_kernel<<<gQ, 256, HSMEM_TOTAL>>>(xnh, xnl, wkh, wkl, bk, nullptr, k, nullptr, nullptr, DMODEL, DMODEL, 0);
    gemm_hmma_kernel<<<gQ, 256, HSMEM_TOTAL>>>(xnh, xnl, wvh, wvl, bv, nullptr, v, nullptr, nullptr, DMODEL, DMODEL, 0);

    // 3. Causal flash attention -> split
    dim3 gA(SEQ / QROWS, BATCH * NHEAD);
    flash_attn_kernel<<<gA, 128>>>(q, k, v, ath, atl);

    // 4. Output projection + residual(x) -> h
    gemm_hmma_kernel<<<gQ, 256, HSMEM_TOTAL>>>(ath, atl, woh, wol, bo, x, h, nullptr, nullptr, DMODEL, DMODEL, 1);

    // 5. LN2 -> split (reuse xn)
    ln_kernel<<<NROWS, 256>>>(h, g2, be2, xnh, xnl);

    // 6. FFN1 + relu -> split
    dim3 gF1(DFF / 128, NROWS / 128);
    gemm_hmma_kernel<<<gF1, 256, HSMEM_TOTAL>>>(xnh, xnl, w1h, w1l, b1, nullptr, nullptr, ffh, ffl, DFF, DMODEL, 2);

    // 7. FFN2 + residual(h) -> out
    dim3 gF2(DMODEL / 128, NROWS / 128);
    gemm_hmma_kernel<<<gF2, 256, HSMEM_TOTAL>>>(ffh, ffl, w2h, w2l, b2, h, out, nullptr, nullptr, DMODEL, DFF, 1);
}

// round 4
// speedup vs baseline: 2.4828x; 1.5242x over previous
#include <cuda_runtime.h>
#include <cuda_bf16.h>
#include <cstdint>
#include <math.h>

// Problem constants
#define BATCH   2
#define SEQ     2048
#define DMODEL  1024
#define NHEAD   16
#define DKH     64
#define DFF     4096
#define NROWS   (BATCH * SEQ)   // 4096

// ===========================================================================
// Helpers
// ===========================================================================
__device__ __forceinline__ uint32_t smem_to_u32(const void* p) {
    uint32_t a;
    asm("{ .reg .u64 t; cvta.to.shared.u64 t, %1; cvt.u32.u64 %0, t; }" : "=r"(a) : "l"(p));
    return a;
}
__device__ __forceinline__ void cp_async16(uint32_t s, const void* g) {
    asm volatile("cp.async.cg.shared.global [%0], [%1], 16;" :: "r"(s), "l"(g));
}
__device__ __forceinline__ void cp_commit() {
    asm volatile("cp.async.commit_group;" ::: "memory");
}
template <int N>
__device__ __forceinline__ void cp_wait() {
    asm volatile("cp.async.wait_group %0;" :: "n"(N) : "memory");
}
__device__ __forceinline__ void ldmx4(uint32_t* r, uint32_t addr) {
    asm volatile("ldmatrix.sync.aligned.m8n8.x4.shared.b16 {%0,%1,%2,%3}, [%4];"
                 : "=r"(r[0]), "=r"(r[1]), "=r"(r[2]), "=r"(r[3]) : "r"(addr));
}
__device__ __forceinline__ void ldmx4t(uint32_t* r, uint32_t addr) {
    asm volatile("ldmatrix.sync.aligned.m8n8.x4.trans.shared.b16 {%0,%1,%2,%3}, [%4];"
                 : "=r"(r[0]), "=r"(r[1]), "=r"(r[2]), "=r"(r[3]) : "r"(addr));
}
__device__ __forceinline__ void mma16816(float* d, const uint32_t* a, const uint32_t* b) {
    asm volatile("mma.sync.aligned.m16n8k16.row.col.f32.bf16.bf16.f32 "
                 "{%0,%1,%2,%3}, {%4,%5,%6,%7}, {%8,%9}, {%0,%1,%2,%3};"
                 : "+f"(d[0]), "+f"(d[1]), "+f"(d[2]), "+f"(d[3])
                 : "r"(a[0]), "r"(a[1]), "r"(a[2]), "r"(a[3]), "r"(b[0]), "r"(b[1]));
}
__device__ __forceinline__ void split2(float v, __nv_bfloat16& h, __nv_bfloat16& l) {
    h = __float2bfloat16(v);
    l = __float2bfloat16(v - __bfloat162float(h));
}
__device__ __forceinline__ void split_pair(float a, float b, uint32_t& hi, uint32_t& lo) {
    __nv_bfloat16 ah, al, bh, bl;
    split2(a, ah, al); split2(b, bh, bl);
    __nv_bfloat162 h2 = __halves2bfloat162(ah, bh);
    __nv_bfloat162 l2 = __halves2bfloat162(al, bl);
    hi = *reinterpret_cast<uint32_t*>(&h2);
    lo = *reinterpret_cast<uint32_t*>(&l2);
}

// ===========================================================================
// Scratch (__device__ globals; no cudaMalloc allowed)
// ===========================================================================
__device__ __nv_bfloat16 g_xnh[NROWS * DMODEL], g_xnl[NROWS * DMODEL];
__device__ __nv_bfloat16 g_ath[NROWS * DMODEL], g_atl[NROWS * DMODEL];
__device__ __nv_bfloat16 g_ffh[NROWS * DFF],    g_ffl[NROWS * DFF];
__device__ __nv_bfloat16 g_qh[NROWS * DMODEL],  g_ql[NROWS * DMODEL];
__device__ __nv_bfloat16 g_kh[NROWS * DMODEL],  g_kl[NROWS * DMODEL];
__device__ __nv_bfloat16 g_vh[NROWS * DMODEL],  g_vl[NROWS * DMODEL];
__device__ __nv_bfloat16 g_wqh[DMODEL * DMODEL], g_wql[DMODEL * DMODEL];
__device__ __nv_bfloat16 g_wkh[DMODEL * DMODEL], g_wkl[DMODEL * DMODEL];
__device__ __nv_bfloat16 g_wvh[DMODEL * DMODEL], g_wvl[DMODEL * DMODEL];
__device__ __nv_bfloat16 g_woh[DMODEL * DMODEL], g_wol[DMODEL * DMODEL];
__device__ __nv_bfloat16 g_w1h[DFF * DMODEL],    g_w1l[DFF * DMODEL];
__device__ __nv_bfloat16 g_w2h[DMODEL * DFF],    g_w2l[DMODEL * DFF];
__device__ float g_h[NROWS * DMODEL];

// ===========================================================================
// Weight transpose + bf16 split: W[K,N] fp32 -> Th/Tl[N,K] bf16
// ===========================================================================
__global__ __launch_bounds__(256) void transpose_split_kernel(
    const float* __restrict__ W, __nv_bfloat16* __restrict__ Th,
    __nv_bfloat16* __restrict__ Tl, int K, int N)
{
    __shared__ float tile[32][33];
    int n0 = blockIdx.x * 32, k0 = blockIdx.y * 32;
    int tx = threadIdx.x & 31, ty = threadIdx.x >> 5;
#pragma unroll
    for (int i = 0; i < 4; i++)
        tile[ty + i * 8][tx] = W[(size_t)(k0 + ty + i * 8) * N + n0 + tx];
    __syncthreads();
#pragma unroll
    for (int i = 0; i < 4; i++) {
        float v = tile[tx][ty + i * 8];
        __nv_bfloat16 h, l;
        split2(v, h, l);
        size_t o = (size_t)(n0 + ty + i * 8) * K + k0 + tx;
        Th[o] = h; Tl[o] = l;
    }
}

// ===========================================================================
// LayerNorm (split bf16 output)
// ===========================================================================
__global__ __launch_bounds__(256) void ln_kernel(
    const float* __restrict__ X, const float* __restrict__ gamma,
    const float* __restrict__ beta, __nv_bfloat16* __restrict__ Yh,
    __nv_bfloat16* __restrict__ Yl)
{
    int row = blockIdx.x;
    int t   = threadIdx.x;
    float4 xv = ((const float4*)(X + (size_t)row * DMODEL))[t];
    float s = xv.x + xv.y + xv.z + xv.w;
    float q = xv.x * xv.x + xv.y * xv.y + xv.z * xv.z + xv.w * xv.w;
#pragma unroll
    for (int off = 16; off > 0; off >>= 1) {
        s += __shfl_xor_sync(0xffffffffu, s, off);
        q += __shfl_xor_sync(0xffffffffu, q, off);
    }
    __shared__ float ss[8], sq[8];
    if ((t & 31) == 0) { ss[t >> 5] = s; sq[t >> 5] = q; }
    __syncthreads();
    __shared__ float smu, srstd;
    if (t == 0) {
        float S = 0.f, Q = 0.f;
#pragma unroll
        for (int i = 0; i < 8; i++) { S += ss[i]; Q += sq[i]; }
        float mu  = S * (1.0f / DMODEL);
        float var = Q * (1.0f / DMODEL) - mu * mu;
        smu = mu; srstd = rsqrtf(var + 1e-5f);
    }
    __syncthreads();
    float mu = smu, r = srstd;
    float4 g4 = ((const float4*)gamma)[t];
    float4 b4 = ((const float4*)beta)[t];
    float y[4];
    y[0] = (xv.x - mu) * r * g4.x + b4.x;
    y[1] = (xv.y - mu) * r * g4.y + b4.y;
    y[2] = (xv.z - mu) * r * g4.z + b4.z;
    y[3] = (xv.w - mu) * r * g4.w + b4.w;
    __nv_bfloat16 h[4], l[4];
#pragma unroll
    for (int i = 0; i < 4; i++) split2(y[i], h[i], l[i]);
    size_t base = (size_t)row * DMODEL + t * 4;
    *(__nv_bfloat162*)(Yh + base)     = __halves2bfloat162(h[0], h[1]);
    *(__nv_bfloat162*)(Yh + base + 2) = __halves2bfloat162(h[2], h[3]);
    *(__nv_bfloat162*)(Yl + base)     = __halves2bfloat162(l[0], l[1]);
    *(__nv_bfloat162*)(Yl + base + 2) = __halves2bfloat162(l[2], l[3]);
}

// ===========================================================================
// HMMA bf16-split GEMM. modes: 0 fp32+bias | 1 fp32+bias+res |
// 2 split-bf16+bias+relu | 3 split-bf16+bias
// ===========================================================================
#define BKC 32
#define TSTRIDE 80
#define TBYTES (128 * TSTRIDE)
#define STG_BYTES (4 * TBYTES)
#define HSMEM_TOTAL (2 * STG_BYTES)

__device__ __forceinline__ void load_stage(
    const __nv_bfloat16* __restrict__ Ah, const __nv_bfloat16* __restrict__ Al,
    const __nv_bfloat16* __restrict__ Bh, const __nv_bfloat16* __restrict__ Bl,
    int m0, int n0, int k0, int K, uint32_t sbase)
{
    int tid = threadIdx.x;
    const __nv_bfloat16* gt[4] = {
        Ah + (size_t)m0 * K, Al + (size_t)m0 * K,
        Bh + (size_t)n0 * K, Bl + (size_t)n0 * K };
#pragma unroll
    for (int T = 0; T < 4; T++) {
#pragma unroll
        for (int j = 0; j < 2; j++) {
            int e = tid + j * 256;
            int row = e >> 2, s = e & 3;
            const void* g = (const char*)(gt[T] + (size_t)row * K + k0) + s * 16;
            cp_async16(sbase + T * TBYTES + row * TSTRIDE + s * 16, g);
        }
    }
}

__global__ __launch_bounds__(256, 1) void gemm_hmma_kernel(
    const __nv_bfloat16* __restrict__ Ah, const __nv_bfloat16* __restrict__ Al,
    const __nv_bfloat16* __restrict__ Bh, const __nv_bfloat16* __restrict__ Bl,
    const float* __restrict__ bias, const float* __restrict__ res,
    float* __restrict__ outF, __nv_bfloat16* __restrict__ outBh,
    __nv_bfloat16* __restrict__ outBl, int N, int K, int mode)
{
    extern __shared__ char smem[];
    uint32_t sb = smem_to_u32(smem);
    int tid = threadIdx.x, wid = tid >> 5, lane = tid & 31;
    int m0 = blockIdx.y * 128, n0 = blockIdx.x * 128;
    int wy = wid >> 2, wx = wid & 3;

    float acc[4][4][4];
#pragma unroll
    for (int a = 0; a < 4; a++)
#pragma unroll
        for (int b = 0; b < 4; b++)
#pragma unroll
            for (int c = 0; c < 4; c++) acc[a][b][c] = 0.f;

    const int NC = K >> 5;

    load_stage(Ah, Al, Bh, Bl, m0, n0, 0, K, sb);
    cp_commit();

    int arow = (lane & 7) + ((lane >> 3) & 1) * 8;
    int akof = (lane >> 4) * 16;
    int brow = (lane & 7) + (lane >> 4) * 8;
    int bkof = ((lane >> 3) & 1) * 16;

    for (int i = 0; i < NC; i++) {
        int s = i & 1;
        if (i + 1 < NC) {
            load_stage(Ah, Al, Bh, Bl, m0, n0, (i + 1) * BKC, K, sb + (s ^ 1) * STG_BYTES);
            cp_commit();
            cp_wait<1>();
        } else {
            cp_wait<0>();
        }
        __syncthreads();

        uint32_t st = sb + s * STG_BYTES;
#pragma unroll
        for (int kh = 0; kh < 2; kh++) {
            uint32_t Afh[4][4], Afl[4][4];
            uint32_t Bfh[4][2], Bfl[4][2];
#pragma unroll
            for (int mt = 0; mt < 4; mt++) {
                uint32_t addr = st + (wy * 64 + mt * 16 + arow) * TSTRIDE + kh * 32 + akof;
                ldmx4(Afh[mt], addr);
                ldmx4(Afl[mt], addr + TBYTES);
            }
#pragma unroll
            for (int ntp = 0; ntp < 2; ntp++) {
                uint32_t addr = st + 2 * TBYTES +
                                (wx * 32 + ntp * 16 + brow) * TSTRIDE + kh * 32 + bkof;
                uint32_t r[4];
                ldmx4(r, addr);
                Bfh[ntp * 2][0] = r[0]; Bfh[ntp * 2][1] = r[1];
                Bfh[ntp * 2 + 1][0] = r[2]; Bfh[ntp * 2 + 1][1] = r[3];
                ldmx4(r, addr + TBYTES);
                Bfl[ntp * 2][0] = r[0]; Bfl[ntp * 2][1] = r[1];
                Bfl[ntp * 2 + 1][0] = r[2]; Bfl[ntp * 2 + 1][1] = r[3];
            }
#pragma unroll
            for (int mt = 0; mt < 4; mt++)
#pragma unroll
                for (int nt = 0; nt < 4; nt++) {
                    mma16816(acc[mt][nt], Afh[mt], Bfh[nt]);
                    mma16816(acc[mt][nt], Afl[mt], Bfh[nt]);
                    mma16816(acc[mt][nt], Afh[mt], Bfl[nt]);
                }
        }
        __syncthreads();
    }

#pragma unroll
    for (int mt = 0; mt < 4; mt++) {
#pragma unroll
        for (int nt = 0; nt < 4; nt++) {
            int r0 = m0 + wy * 64 + mt * 16 + (lane >> 2);
            int c  = n0 + wx * 32 + nt * 8 + (lane & 3) * 2;
            float b0 = bias[c], b1 = bias[c + 1];
#pragma unroll
            for (int half = 0; half < 2; half++) {
                int r = r0 + half * 8;
                float v0 = acc[mt][nt][half * 2 + 0] + b0;
                float v1 = acc[mt][nt][half * 2 + 1] + b1;
                size_t o = (size_t)r * N + c;
                if (mode >= 2) {
                    if (mode == 2) { v0 = fmaxf(v0, 0.f); v1 = fmaxf(v1, 0.f); }
                    uint32_t hi, lo;
                    split_pair(v0, v1, hi, lo);
                    *(uint32_t*)(outBh + o) = hi;
                    *(uint32_t*)(outBl + o) = lo;
                } else {
                    if (mode == 1) {
                        float2 rr = *(const float2*)(res + o);
                        v0 += rr.x; v1 += rr.y;
                    }
                    float2 w; w.x = v0; w.y = v1;
                    *(float2*)(outF + o) = w;
                }
            }
        }
    }
}

// ===========================================================================
// HMMA flash attention (causal), split-3 bf16, split-bf16 in/out.
// Block: 256 threads (8 warps), 128 q-rows (16/warp), KV tiles of 64.
// ===========================================================================
#define AQ 128
#define ATK 64
#define ASTR 144                              // 64 bf16 = 128B + 16 pad
#define A_QH 0
#define A_QL (128 * ASTR)                     // 18432
#define A_ST (2 * 128 * ASTR)                 // 36864
#define A_STG (4 * 64 * ASTR)                 // 36864 per stage
#define A_KL (64 * ASTR)
#define A_VH (2 * 64 * ASTR)
#define A_VL (3 * 64 * ASTR)
#define ATT_SMEM (A_ST + 2 * A_STG)           // 110592

__device__ __forceinline__ void load_kv_tile(
    const __nv_bfloat16* __restrict__ kh, const __nv_bfloat16* __restrict__ kl,
    const __nv_bfloat16* __restrict__ vh, const __nv_bfloat16* __restrict__ vl,
    size_t gbase, int k0, uint32_t sbase)
{
    int tid = threadIdx.x;
#pragma unroll
    for (int j = 0; j < 2; j++) {
        int e = tid + j * 256;
        int row = e >> 3, ch = e & 7;
        size_t g = gbase + (size_t)(k0 + row) * DMODEL + ch * 8;
        uint32_t so = row * ASTR + ch * 16;
        cp_async16(sbase + so,         kh + g);
        cp_async16(sbase + A_KL + so,  kl + g);
        cp_async16(sbase + A_VH + so,  vh + g);
        cp_async16(sbase + A_VL + so,  vl + g);
    }
}

__global__ __launch_bounds__(256, 1) void flash_hmma_kernel(
    const __nv_bfloat16* __restrict__ qh, const __nv_bfloat16* __restrict__ ql,
    const __nv_bfloat16* __restrict__ kh, const __nv_bfloat16* __restrict__ kl,
    const __nv_bfloat16* __restrict__ vh, const __nv_bfloat16* __restrict__ vl,
    __nv_bfloat16* __restrict__ Oh, __nv_bfloat16* __restrict__ Ol)
{
    extern __shared__ char smem[];
    uint32_t sb = smem_to_u32(smem);
    int tid = threadIdx.x, wid = tid >> 5, lane = tid & 31;
    int bh = blockIdx.y, b = bh >> 4, h = bh & 15;
    int q0 = blockIdx.x * AQ;
    size_t gbase = (size_t)(b * SEQ) * DMODEL + h * DKH;

    // Load Q tile (hi+lo)
#pragma unroll
    for (int j = 0; j < 4; j++) {
        int e = tid + j * 256;
        int row = e >> 3, ch = e & 7;
        size_t g = gbase + (size_t)(q0 + row) * DMODEL + ch * 8;
        cp_async16(sb + A_QH + row * ASTR + ch * 16, qh + g);
        cp_async16(sb + A_QL + row * ASTR + ch * 16, ql + g);
    }
    load_kv_tile(kh, kl, vh, vl, gbase, 0, sb + A_ST);
    cp_commit();

    const int ntiles = q0 / ATK + 2;

    float Sv[32], Oa[32];
#pragma unroll
    for (int i = 0; i < 32; i++) Oa[i] = 0.f;
    float m0 = -1e30f, m1 = -1e30f, l0 = 0.f, l1 = 0.f;

    int arow = (lane & 7) + ((lane >> 3) & 1) * 8;
    int akof = (lane >> 4) * 16;
    int brow = (lane & 7) + (lane >> 4) * 8;
    int bkof = ((lane >> 3) & 1) * 16;
    int vrow = (lane & 7) + ((lane >> 3) & 1) * 8;
    int vbyt = (lane >> 4) * 16;

    int wq = q0 + (wid << 4);
    int qrow0 = wq + (lane >> 2);

    for (int jt = 0; jt < ntiles; jt++) {
        int s = jt & 1;
        if (jt + 1 < ntiles) {
            load_kv_tile(kh, kl, vh, vl, gbase, (jt + 1) * ATK,
                         sb + A_ST + (s ^ 1) * A_STG);
            cp_commit();
            cp_wait<1>();
        } else {
            cp_wait<0>();
        }
        __syncthreads();

        int k0 = jt * ATK;
        if (k0 <= wq + 15) {
            uint32_t stk = sb + A_ST + s * A_STG;
#pragma unroll
            for (int i = 0; i < 32; i++) Sv[i] = 0.f;
            // --- scores: Q x K^T (split-3) ---
#pragma unroll
            for (int ks = 0; ks < 4; ks++) {
                uint32_t qfh[4], qfl[4];
                uint32_t qaddr = sb + A_QH + (wid * 16 + arow) * ASTR + ks * 32 + akof;
                ldmx4(qfh, qaddr);
                ldmx4(qfl, qaddr + A_QL);
#pragma unroll
                for (int g = 0; g < 4; g++) {
                    uint32_t kfh[4], kfl[4];
                    uint32_t kaddr = stk + (g * 16 + brow) * ASTR + ks * 32 + bkof;
                    ldmx4(kfh, kaddr);
                    ldmx4(kfl, kaddr + A_KL);
                    mma16816(&Sv[(g * 2) * 4],     qfh, &kfh[0]);
                    mma16816(&Sv[(g * 2) * 4],     qfl, &kfh[0]);
                    mma16816(&Sv[(g * 2) * 4],     qfh, &kfl[0]);
                    mma16816(&Sv[(g * 2 + 1) * 4], qfh, &kfh[2]);
                    mma16816(&Sv[(g * 2 + 1) * 4], qfl, &kfh[2]);
                    mma16816(&Sv[(g * 2 + 1) * 4], qfh, &kfl[2]);
                }
            }
            // --- scale + causal mask ---
            int keyb = k0 + ((lane & 3) << 1);
#pragma unroll
            for (int j = 0; j < 8; j++) {
                int key = keyb + j * 8;
                float s0 = Sv[j * 4 + 0] * 0.125f; if (key     > qrow0)     s0 = -1e9f;
                float s1 = Sv[j * 4 + 1] * 0.125f; if (key + 1 > qrow0)     s1 = -1e9f;
                float s2 = Sv[j * 4 + 2] * 0.125f; if (key     > qrow0 + 8) s2 = -1e9f;
                float s3 = Sv[j * 4 + 3] * 0.125f; if (key + 1 > qrow0 + 8) s3 = -1e9f;
                Sv[j * 4 + 0] = s0; Sv[j * 4 + 1] = s1;
                Sv[j * 4 + 2] = s2; Sv[j * 4 + 3] = s3;
            }
            // --- online softmax ---
            float mt0 = -1e30f, mt1 = -1e30f;
#pragma unroll
            for (int j = 0; j < 8; j++) {
                mt0 = fmaxf(mt0, fmaxf(Sv[j * 4 + 0], Sv[j * 4 + 1]));
                mt1 = fmaxf(mt1, fmaxf(Sv[j * 4 + 2], Sv[j * 4 + 3]));
            }
            mt0 = fmaxf(mt0, __shfl_xor_sync(0xffffffffu, mt0, 1));
            mt0 = fmaxf(mt0, __shfl_xor_sync(0xffffffffu, mt0, 2));
            mt1 = fmaxf(mt1, __shfl_xor_sync(0xffffffffu, mt1, 1));
            mt1 = fmaxf(mt1, __shfl_xor_sync(0xffffffffu, mt1, 2));
            float mn0 = fmaxf(m0, mt0), mn1 = fmaxf(m1, mt1);
            float c0 = __expf(m0 - mn0), c1 = __expf(m1 - mn1);
            l0 *= c0; l1 *= c1;
#pragma unroll
            for (int j = 0; j < 8; j++) {
                Oa[j * 4 + 0] *= c0; Oa[j * 4 + 1] *= c0;
                Oa[j * 4 + 2] *= c1; Oa[j * 4 + 3] *= c1;
            }
            float sum0 = 0.f, sum1 = 0.f;
#pragma unroll
            for (int j = 0; j < 8; j++) {
                float p0 = __expf(Sv[j * 4 + 0] - mn0);
                float p1 = __expf(Sv[j * 4 + 1] - mn0);
                float p2 = __expf(Sv[j * 4 + 2] - mn1);
                float p3 = __expf(Sv[j * 4 + 3] - mn1);
                Sv[j * 4 + 0] = p0; Sv[j * 4 + 1] = p1;
                Sv[j * 4 + 2] = p2; Sv[j * 4 + 3] = p3;
                sum0 += p0 + p1; sum1 += p2 + p3;
            }
            sum0 += __shfl_xor_sync(0xffffffffu, sum0, 1);
            sum0 += __shfl_xor_sync(0xffffffffu, sum0, 2);
            sum1 += __shfl_xor_sync(0xffffffffu, sum1, 1);
            sum1 += __shfl_xor_sync(0xffffffffu, sum1, 2);
            l0 += sum0; l1 += sum1;
            m0 = mn0; m1 = mn1;
            // --- P x V (split-3) ---
#pragma unroll
            for (int ks = 0; ks < 4; ks++) {
                uint32_t ph[4], pl[4];
                split_pair(Sv[8 * ks + 0], Sv[8 * ks + 1], ph[0], pl[0]);
                split_pair(Sv[8 * ks + 2], Sv[8 * ks + 3], ph[1], pl[1]);
                split_pair(Sv[8 * ks + 4], Sv[8 * ks + 5], ph[2], pl[2]);
                split_pair(Sv[8 * ks + 6], Sv[8 * ks + 7], ph[3], pl[3]);
#pragma unroll
                for (int nt = 0; nt < 4; nt++) {
                    uint32_t vfh[4], vfl[4];
                    uint32_t vaddr = stk + A_VH + (ks * 16 + vrow) * ASTR + nt * 32 + vbyt;
                    ldmx4t(vfh, vaddr);
                    ldmx4t(vfl, vaddr + (A_VL - A_VH));
                    mma16816(&Oa[(nt * 2) * 4],     ph, &vfh[0]);
                    mma16816(&Oa[(nt * 2) * 4],     pl, &vfh[0]);
                    mma16816(&Oa[(nt * 2) * 4],     ph, &vfl[0]);
                    mma16816(&Oa[(nt * 2 + 1) * 4], ph, &vfh[2]);
                    mma16816(&Oa[(nt * 2 + 1) * 4], pl, &vfh[2]);
                    mma16816(&Oa[(nt * 2 + 1) * 4], ph, &vfl[2]);
                }
            }
        }
        __syncthreads();
    }

    // Epilogue: normalize + split-bf16 store
    float inv0 = 1.f / l0, inv1 = 1.f / l1;
    size_t r0 = gbase + (size_t)qrow0 * DMODEL;
    size_t r1 = gbase + (size_t)(qrow0 + 8) * DMODEL;
#pragma unroll
    for (int nt = 0; nt < 8; nt++) {
        int col = nt * 8 + (lane & 3) * 2;
        uint32_t hi, lo;
        split_pair(Oa[nt * 4 + 0] * inv0, Oa[nt * 4 + 1] * inv0, hi, lo);
        *(uint32_t*)(Oh + r0 + col) = hi;
        *(uint32_t*)(Ol + r0 + col) = lo;
        split_pair(Oa[nt * 4 + 2] * inv1, Oa[nt * 4 + 3] * inv1, hi, lo);
        *(uint32_t*)(Oh + r1 + col) = hi;
        *(uint32_t*)(Ol + r1 + col) = lo;
    }
}

// ===========================================================================
// Launcher
// ===========================================================================
extern "C" void kernel_launch(void* const* d_in, const int* in_sizes, int n_in,
                              void* d_out, int out_size)
{
    const float* x   = (const float*)d_in[0];
    const float* Wq  = (const float*)d_in[2];
    const float* bq  = (const float*)d_in[3];
    const float* Wk  = (const float*)d_in[4];
    const float* bk  = (const float*)d_in[5];
    const float* Wv  = (const float*)d_in[6];
    const float* bv  = (const float*)d_in[7];
    const float* Wo  = (const float*)d_in[8];
    const float* bo  = (const float*)d_in[9];
    const float* W1  = (const float*)d_in[10];
    const float* b1  = (const float*)d_in[11];
    const float* W2  = (const float*)d_in[12];
    const float* b2  = (const float*)d_in[13];
    const float* g1  = (const float*)d_in[14];
    const float* be1 = (const float*)d_in[15];
    const float* g2  = (const float*)d_in[16];
    const float* be2 = (const float*)d_in[17];
    float* out = (float*)d_out;

    __nv_bfloat16 *xnh, *xnl, *ath, *atl, *ffh, *ffl;
    __nv_bfloat16 *qh, *ql, *kh, *kl, *vh, *vl;
    __nv_bfloat16 *wqh, *wql, *wkh, *wkl, *wvh, *wvl, *woh, *wol, *w1h, *w1l, *w2h, *w2l;
    float *h;
    cudaGetSymbolAddress((void**)&xnh, g_xnh); cudaGetSymbolAddress((void**)&xnl, g_xnl);
    cudaGetSymbolAddress((void**)&ath, g_ath); cudaGetSymbolAddress((void**)&atl, g_atl);
    cudaGetSymbolAddress((void**)&ffh, g_ffh); cudaGetSymbolAddress((void**)&ffl, g_ffl);
    cudaGetSymbolAddress((void**)&qh, g_qh); cudaGetSymbolAddress((void**)&ql, g_ql);
    cudaGetSymbolAddress((void**)&kh, g_kh); cudaGetSymbolAddress((void**)&kl, g_kl);
    cudaGetSymbolAddress((void**)&vh, g_vh); cudaGetSymbolAddress((void**)&vl, g_vl);
    cudaGetSymbolAddress((void**)&wqh, g_wqh); cudaGetSymbolAddress((void**)&wql, g_wql);
    cudaGetSymbolAddress((void**)&wkh, g_wkh); cudaGetSymbolAddress((void**)&wkl, g_wkl);
    cudaGetSymbolAddress((void**)&wvh, g_wvh); cudaGetSymbolAddress((void**)&wvl, g_wvl);
    cudaGetSymbolAddress((void**)&woh, g_woh); cudaGetSymbolAddress((void**)&wol, g_wol);
    cudaGetSymbolAddress((void**)&w1h, g_w1h); cudaGetSymbolAddress((void**)&w1l, g_w1l);
    cudaGetSymbolAddress((void**)&w2h, g_w2h); cudaGetSymbolAddress((void**)&w2l, g_w2l);
    cudaGetSymbolAddress((void**)&h, g_h);

    cudaFuncSetAttribute(gemm_hmma_kernel,
                         cudaFuncAttributeMaxDynamicSharedMemorySize, HSMEM_TOTAL);
    cudaFuncSetAttribute(flash_hmma_kernel,
                         cudaFuncAttributeMaxDynamicSharedMemorySize, ATT_SMEM);

    // Weight transpose + split
    dim3 tb(256);
    transpose_split_kernel<<<dim3(DMODEL / 32, DMODEL / 32), tb>>>(Wq, wqh, wql, DMODEL, DMODEL);
    transpose_split_kernel<<<dim3(DMODEL / 32, DMODEL / 32), tb>>>(Wk, wkh, wkl, DMODEL, DMODEL);
    transpose_split_kernel<<<dim3(DMODEL / 32, DMODEL / 32), tb>>>(Wv, wvh, wvl, DMODEL, DMODEL);
    transpose_split_kernel<<<dim3(DMODEL / 32, DMODEL / 32), tb>>>(Wo, woh, wol, DMODEL, DMODEL);
    transpose_split_kernel<<<dim3(DFF / 32, DMODEL / 32), tb>>>(W1, w1h, w1l, DMODEL, DFF);
    transpose_split_kernel<<<dim3(DMODEL / 32, DFF / 32), tb>>>(W2, w2h, w2l, DFF, DMODEL);

    // 1. LN1 -> split
    ln_kernel<<<NROWS, 256>>>(x, g1, be1, xnh, xnl);

    // 2. QKV projections -> split-bf16 outputs (mode 3)
    dim3 gQ(DMODEL / 128, NROWS / 128);
    gemm_hmma_kernel<<<gQ, 256, HSMEM_TOTAL>>>(xnh, xnl, wqh, wql, bq, nullptr, nullptr, qh, ql, DMODEL, DMODEL, 3);
    gemm_hmma_kernel<<<gQ, 256, HSMEM_TOTAL>>>(xnh, xnl, wkh, wkl, bk, nullptr, nullptr, kh, kl, DMODEL, DMODEL, 3);
    gemm_hmma_kernel<<<gQ, 256, HSMEM_TOTAL>>>(xnh, xnl, wvh, wvl, bv, nullptr, nullptr, vh, vl, DMODEL, DMODEL, 3);

    // 3. Causal flash attention (HMMA) -> split
    dim3 gA(SEQ / AQ, BATCH * NHEAD);
    flash_hmma_kernel<<<gA, 256, ATT_SMEM>>>(qh, ql, kh, kl, vh, vl, ath, atl);

    // 4. Output projection + residual(x) -> h
    gemm_hmma_kernel<<<gQ, 256, HSMEM_TOTAL>>>(ath, atl, woh, wol, bo, x, h, nullptr, nullptr, DMODEL, DMODEL, 1);

    // 5. LN2 -> split
    ln_kernel<<<NROWS, 256>>>(h, g2, be2, xnh, xnl);

    // 6. FFN1 + relu -> split
    dim3 gF1(DFF / 128, NROWS / 128);
    gemm_hmma_kernel<<<gF1, 256, HSMEM_TOTAL>>>(xnh, xnl, w1h, w1l, b1, nullptr, nullptr, ffh, ffl, DFF, DMODEL, 2);

    // 7. FFN2 + residual(h) -> out
    dim3 gF2(DMODEL / 128, NROWS / 128);
    gemm_hmma_kernel<<<gF2, 256, HSMEM_TOTAL>>>(ffh, ffl, w2h, w2l, b2, h, out, nullptr, nullptr, DMODEL, DFF, 1);
}

// round 5
// speedup vs baseline: 2.8099x; 1.1317x over previous
#include <cuda_runtime.h>
#include <cuda_bf16.h>
#include <cstdint>
#include <math.h>

// Problem constants
#define BATCH   2
#define SEQ     2048
#define DMODEL  1024
#define NHEAD   16
#define DKH     64
#define DFF     4096
#define NROWS   (BATCH * SEQ)   // 4096
#define NQKV    3072            // fused QKV output width

// ===========================================================================
// Helpers
// ===========================================================================
__device__ __forceinline__ uint32_t smem_to_u32(const void* p) {
    uint32_t a;
    asm("{ .reg .u64 t; cvta.to.shared.u64 t, %1; cvt.u32.u64 %0, t; }" : "=r"(a) : "l"(p));
    return a;
}
__device__ __forceinline__ void cp_async16(uint32_t s, const void* g) {
    asm volatile("cp.async.cg.shared.global [%0], [%1], 16;" :: "r"(s), "l"(g));
}
__device__ __forceinline__ void cp_commit() {
    asm volatile("cp.async.commit_group;" ::: "memory");
}
template <int N>
__device__ __forceinline__ void cp_wait() {
    asm volatile("cp.async.wait_group %0;" :: "n"(N) : "memory");
}
__device__ __forceinline__ void ldmx4(uint32_t* r, uint32_t addr) {
    asm volatile("ldmatrix.sync.aligned.m8n8.x4.shared.b16 {%0,%1,%2,%3}, [%4];"
                 : "=r"(r[0]), "=r"(r[1]), "=r"(r[2]), "=r"(r[3]) : "r"(addr));
}
__device__ __forceinline__ void ldmx4t(uint32_t* r, uint32_t addr) {
    asm volatile("ldmatrix.sync.aligned.m8n8.x4.trans.shared.b16 {%0,%1,%2,%3}, [%4];"
                 : "=r"(r[0]), "=r"(r[1]), "=r"(r[2]), "=r"(r[3]) : "r"(addr));
}
__device__ __forceinline__ void mma16816(float* d, const uint32_t* a, const uint32_t* b) {
    asm volatile("mma.sync.aligned.m16n8k16.row.col.f32.bf16.bf16.f32 "
                 "{%0,%1,%2,%3}, {%4,%5,%6,%7}, {%8,%9}, {%0,%1,%2,%3};"
                 : "+f"(d[0]), "+f"(d[1]), "+f"(d[2]), "+f"(d[3])
                 : "r"(a[0]), "r"(a[1]), "r"(a[2]), "r"(a[3]), "r"(b[0]), "r"(b[1]));
}
__device__ __forceinline__ void split2(float v, __nv_bfloat16& h, __nv_bfloat16& l) {
    h = __float2bfloat16(v);
    l = __float2bfloat16(v - __bfloat162float(h));
}
__device__ __forceinline__ void split_pair(float a, float b, uint32_t& hi, uint32_t& lo) {
    __nv_bfloat16 ah, al, bh, bl;
    split2(a, ah, al); split2(b, bh, bl);
    __nv_bfloat162 h2 = __halves2bfloat162(ah, bh);
    __nv_bfloat162 l2 = __halves2bfloat162(al, bl);
    hi = *reinterpret_cast<uint32_t*>(&h2);
    lo = *reinterpret_cast<uint32_t*>(&l2);
}

// ===========================================================================
// Scratch (__device__ globals; no cudaMalloc allowed)
// ===========================================================================
__device__ __nv_bfloat16 g_xnh[NROWS * DMODEL], g_xnl[NROWS * DMODEL];
__device__ __nv_bfloat16 g_ath[NROWS * DMODEL], g_atl[NROWS * DMODEL];
__device__ __nv_bfloat16 g_ffh[NROWS * DFF],    g_ffl[NROWS * DFF];
__device__ __nv_bfloat16 g_qkvh[NROWS * NQKV],  g_qkvl[NROWS * NQKV];
// 4 square weights transposed, contiguous: [WqT | WkT | WvT | WoT]
__device__ __nv_bfloat16 g_wcath[4 * DMODEL * DMODEL], g_wcatl[4 * DMODEL * DMODEL];
__device__ __nv_bfloat16 g_w1h[DFF * DMODEL],    g_w1l[DFF * DMODEL];
__device__ __nv_bfloat16 g_w2h[DMODEL * DFF],    g_w2l[DMODEL * DFF];
__device__ float g_bqkv[NQKV];
__device__ float g_h[NROWS * DMODEL];

// ===========================================================================
// Bias concat: [bq | bk | bv]
// ===========================================================================
__global__ void concat_bias_kernel(const float* __restrict__ bq,
                                   const float* __restrict__ bk,
                                   const float* __restrict__ bv,
                                   float* __restrict__ o)
{
    int i = blockIdx.x * blockDim.x + threadIdx.x;
    if (i < 1024)      o[i] = bq[i];
    else if (i < 2048) o[i] = bk[i - 1024];
    else               o[i] = bv[i - 2048];
}

// ===========================================================================
// Weight transpose + bf16 split: W[K,N] fp32 -> Th/Tl[N,K] bf16
// ===========================================================================
__global__ __launch_bounds__(256) void transpose_split_kernel(
    const float* __restrict__ W, __nv_bfloat16* __restrict__ Th,
    __nv_bfloat16* __restrict__ Tl, int K, int N)
{
    __shared__ float tile[32][33];
    int n0 = blockIdx.x * 32, k0 = blockIdx.y * 32;
    int tx = threadIdx.x & 31, ty = threadIdx.x >> 5;
#pragma unroll
    for (int i = 0; i < 4; i++)
        tile[ty + i * 8][tx] = W[(size_t)(k0 + ty + i * 8) * N + n0 + tx];
    __syncthreads();
#pragma unroll
    for (int i = 0; i < 4; i++) {
        float v = tile[tx][ty + i * 8];
        __nv_bfloat16 h, l;
        split2(v, h, l);
        size_t o = (size_t)(n0 + ty + i * 8) * K + k0 + tx;
        Th[o] = h; Tl[o] = l;
    }
}

// Batched version for the four 1024x1024 weights.
__global__ __launch_bounds__(256) void transpose_split4_kernel(
    const float* __restrict__ W0, const float* __restrict__ W1x,
    const float* __restrict__ W2x, const float* __restrict__ W3x,
    __nv_bfloat16* __restrict__ Th, __nv_bfloat16* __restrict__ Tl)
{
    __shared__ float tile[32][33];
    int z = blockIdx.z;
    const float* W = (z == 0) ? W0 : (z == 1) ? W1x : (z == 2) ? W2x : W3x;
    size_t zoff = (size_t)z * DMODEL * DMODEL;
    int n0 = blockIdx.x * 32, k0 = blockIdx.y * 32;
    int tx = threadIdx.x & 31, ty = threadIdx.x >> 5;
#pragma unroll
    for (int i = 0; i < 4; i++)
        tile[ty + i * 8][tx] = W[(size_t)(k0 + ty + i * 8) * DMODEL + n0 + tx];
    __syncthreads();
#pragma unroll
    for (int i = 0; i < 4; i++) {
        float v = tile[tx][ty + i * 8];
        __nv_bfloat16 h, l;
        split2(v, h, l);
        size_t o = zoff + (size_t)(n0 + ty + i * 8) * DMODEL + k0 + tx;
        Th[o] = h; Tl[o] = l;
    }
}

// ===========================================================================
// LayerNorm (split bf16 output)
// ===========================================================================
__global__ __launch_bounds__(256) void ln_kernel(
    const float* __restrict__ X, const float* __restrict__ gamma,
    const float* __restrict__ beta, __nv_bfloat16* __restrict__ Yh,
    __nv_bfloat16* __restrict__ Yl)
{
    int row = blockIdx.x;
    int t   = threadIdx.x;
    float4 xv = ((const float4*)(X + (size_t)row * DMODEL))[t];
    float s = xv.x + xv.y + xv.z + xv.w;
    float q = xv.x * xv.x + xv.y * xv.y + xv.z * xv.z + xv.w * xv.w;
#pragma unroll
    for (int off = 16; off > 0; off >>= 1) {
        s += __shfl_xor_sync(0xffffffffu, s, off);
        q += __shfl_xor_sync(0xffffffffu, q, off);
    }
    __shared__ float ss[8], sq[8];
    if ((t & 31) == 0) { ss[t >> 5] = s; sq[t >> 5] = q; }
    __syncthreads();
    __shared__ float smu, srstd;
    if (t == 0) {
        float S = 0.f, Q = 0.f;
#pragma unroll
        for (int i = 0; i < 8; i++) { S += ss[i]; Q += sq[i]; }
        float mu  = S * (1.0f / DMODEL);
        float var = Q * (1.0f / DMODEL) - mu * mu;
        smu = mu; srstd = rsqrtf(var + 1e-5f);
    }
    __syncthreads();
    float mu = smu, r = srstd;
    float4 g4 = ((const float4*)gamma)[t];
    float4 b4 = ((const float4*)beta)[t];
    float y[4];
    y[0] = (xv.x - mu) * r * g4.x + b4.x;
    y[1] = (xv.y - mu) * r * g4.y + b4.y;
    y[2] = (xv.z - mu) * r * g4.z + b4.z;
    y[3] = (xv.w - mu) * r * g4.w + b4.w;
    __nv_bfloat16 h[4], l[4];
#pragma unroll
    for (int i = 0; i < 4; i++) split2(y[i], h[i], l[i]);
    size_t base = (size_t)row * DMODEL + t * 4;
    *(__nv_bfloat162*)(Yh + base)     = __halves2bfloat162(h[0], h[1]);
    *(__nv_bfloat162*)(Yh + base + 2) = __halves2bfloat162(h[2], h[3]);
    *(__nv_bfloat162*)(Yl + base)     = __halves2bfloat162(l[0], l[1]);
    *(__nv_bfloat162*)(Yl + base + 2) = __halves2bfloat162(l[2], l[3]);
}

// ===========================================================================
// HMMA bf16-split GEMM. 128x128 CTA tile, 8 warps, warp tile 64x32.
// K chunk 64, 2-stage cp.async double buffer.
// modes: 0 fp32+bias | 1 fp32+bias+res | 2 split-bf16+bias+relu | 3 split-bf16+bias
// ===========================================================================
#define BKC 64
#define TSTRIDE 144                    // 64 bf16 = 128B + 16B pad
#define TBYTES (128 * TSTRIDE)         // 18432
#define STG_BYTES (4 * TBYTES)         // 73728: Ah, Al, Bh, Bl
#define HSMEM_TOTAL (2 * STG_BYTES)    // 147456

__device__ __forceinline__ void load_stage(
    const __nv_bfloat16* __restrict__ Ah, const __nv_bfloat16* __restrict__ Al,
    const __nv_bfloat16* __restrict__ Bh, const __nv_bfloat16* __restrict__ Bl,
    int m0, int n0, int k0, int K, uint32_t sbase)
{
    int tid = threadIdx.x;
    const __nv_bfloat16* gt[4] = {
        Ah + (size_t)m0 * K, Al + (size_t)m0 * K,
        Bh + (size_t)n0 * K, Bl + (size_t)n0 * K };
#pragma unroll
    for (int T = 0; T < 4; T++) {
#pragma unroll
        for (int j = 0; j < 4; j++) {
            int e = tid + j * 256;          // 0..1023
            int row = e >> 3, s = e & 7;
            const void* g = (const char*)(gt[T] + (size_t)row * K + k0) + s * 16;
            cp_async16(sbase + T * TBYTES + row * TSTRIDE + s * 16, g);
        }
    }
}

__global__ __launch_bounds__(256, 1) void gemm_hmma_kernel(
    const __nv_bfloat16* __restrict__ Ah, const __nv_bfloat16* __restrict__ Al,
    const __nv_bfloat16* __restrict__ Bh, const __nv_bfloat16* __restrict__ Bl,
    const float* __restrict__ bias, const float* __restrict__ res,
    float* __restrict__ outF, __nv_bfloat16* __restrict__ outBh,
    __nv_bfloat16* __restrict__ outBl, int N, int K, int mode)
{
    extern __shared__ char smem[];
    uint32_t sb = smem_to_u32(smem);
    int tid = threadIdx.x, wid = tid >> 5, lane = tid & 31;
    int m0 = blockIdx.y * 128, n0 = blockIdx.x * 128;
    int wy = wid >> 2, wx = wid & 3;

    float acc[4][4][4];
#pragma unroll
    for (int a = 0; a < 4; a++)
#pragma unroll
        for (int b = 0; b < 4; b++)
#pragma unroll
            for (int c = 0; c < 4; c++) acc[a][b][c] = 0.f;

    const int NC = K >> 6;

    load_stage(Ah, Al, Bh, Bl, m0, n0, 0, K, sb);
    cp_commit();

    int arow = (lane & 7) + ((lane >> 3) & 1) * 8;
    int akof = (lane >> 4) * 16;
    int brow = (lane & 7) + (lane >> 4) * 8;
    int bkof = ((lane >> 3) & 1) * 16;

    for (int i = 0; i < NC; i++) {
        int s = i & 1;
        if (i + 1 < NC) {
            load_stage(Ah, Al, Bh, Bl, m0, n0, (i + 1) * BKC, K, sb + (s ^ 1) * STG_BYTES);
            cp_commit();
            cp_wait<1>();
        } else {
            cp_wait<0>();
        }
        __syncthreads();

        uint32_t st = sb + s * STG_BYTES;
#pragma unroll
        for (int kh = 0; kh < 4; kh++) {
            uint32_t Afh[4][4], Afl[4][4];
            uint32_t Bfh[4][2], Bfl[4][2];
#pragma unroll
            for (int mt = 0; mt < 4; mt++) {
                uint32_t addr = st + (wy * 64 + mt * 16 + arow) * TSTRIDE + kh * 32 + akof;
                ldmx4(Afh[mt], addr);
                ldmx4(Afl[mt], addr + TBYTES);
            }
#pragma unroll
            for (int ntp = 0; ntp < 2; ntp++) {
                uint32_t addr = st + 2 * TBYTES +
                                (wx * 32 + ntp * 16 + brow) * TSTRIDE + kh * 32 + bkof;
                uint32_t r[4];
                ldmx4(r, addr);
                Bfh[ntp * 2][0] = r[0]; Bfh[ntp * 2][1] = r[1];
                Bfh[ntp * 2 + 1][0] = r[2]; Bfh[ntp * 2 + 1][1] = r[3];
                ldmx4(r, addr + TBYTES);
                Bfl[ntp * 2][0] = r[0]; Bfl[ntp * 2][1] = r[1];
                Bfl[ntp * 2 + 1][0] = r[2]; Bfl[ntp * 2 + 1][1] = r[3];
            }
#pragma unroll
            for (int mt = 0; mt < 4; mt++)
#pragma unroll
                for (int nt = 0; nt < 4; nt++) {
                    mma16816(acc[mt][nt], Afh[mt], Bfh[nt]);
                    mma16816(acc[mt][nt], Afl[mt], Bfh[nt]);
                    mma16816(acc[mt][nt], Afh[mt], Bfl[nt]);
                }
        }
        __syncthreads();
    }

#pragma unroll
    for (int mt = 0; mt < 4; mt++) {
#pragma unroll
        for (int nt = 0; nt < 4; nt++) {
            int r0 = m0 + wy * 64 + mt * 16 + (lane >> 2);
            int c  = n0 + wx * 32 + nt * 8 + (lane & 3) * 2;
            float b0 = bias[c], b1 = bias[c + 1];
#pragma unroll
            for (int half = 0; half < 2; half++) {
                int r = r0 + half * 8;
                float v0 = acc[mt][nt][half * 2 + 0] + b0;
                float v1 = acc[mt][nt][half * 2 + 1] + b1;
                size_t o = (size_t)r * N + c;
                if (mode >= 2) {
                    if (mode == 2) { v0 = fmaxf(v0, 0.f); v1 = fmaxf(v1, 0.f); }
                    uint32_t hi, lo;
                    split_pair(v0, v1, hi, lo);
                    *(uint32_t*)(outBh + o) = hi;
                    *(uint32_t*)(outBl + o) = lo;
                } else {
                    if (mode == 1) {
                        float2 rr = *(const float2*)(res + o);
                        v0 += rr.x; v1 += rr.y;
                    }
                    float2 w; w.x = v0; w.y = v1;
                    *(float2*)(outF + o) = w;
                }
            }
        }
    }
}

// ===========================================================================
// HMMA flash attention (causal), split-3 bf16, reads fused QKV (stride 3072).
// Block: 256 threads (8 warps), 128 q-rows (16/warp), KV tiles of 64.
// ===========================================================================
#define AQ 128
#define ATK 64
#define ASTR 144
#define A_QH 0
#define A_QL (128 * ASTR)
#define A_ST (2 * 128 * ASTR)
#define A_STG (4 * 64 * ASTR)
#define A_KL (64 * ASTR)
#define A_VH (2 * 64 * ASTR)
#define A_VL (3 * 64 * ASTR)
#define ATT_SMEM (A_ST + 2 * A_STG)

__device__ __forceinline__ void load_kv_tile(
    const __nv_bfloat16* __restrict__ kh, const __nv_bfloat16* __restrict__ kl,
    const __nv_bfloat16* __restrict__ vh, const __nv_bfloat16* __restrict__ vl,
    size_t gbase, int k0, uint32_t sbase)
{
    int tid = threadIdx.x;
#pragma unroll
    for (int j = 0; j < 2; j++) {
        int e = tid + j * 256;
        int row = e >> 3, ch = e & 7;
        size_t g = gbase + (size_t)(k0 + row) * NQKV + ch * 8;
        uint32_t so = row * ASTR + ch * 16;
        cp_async16(sbase + so,         kh + g);
        cp_async16(sbase + A_KL + so,  kl + g);
        cp_async16(sbase + A_VH + so,  vh + g);
        cp_async16(sbase + A_VL + so,  vl + g);
    }
}

__global__ __launch_bounds__(256, 1) void flash_hmma_kernel(
    const __nv_bfloat16* __restrict__ qkvh, const __nv_bfloat16* __restrict__ qkvl,
    __nv_bfloat16* __restrict__ Oh, __nv_bfloat16* __restrict__ Ol)
{
    extern __shared__ char smem[];
    uint32_t sb = smem_to_u32(smem);
    int tid = threadIdx.x, wid = tid >> 5, lane = tid & 31;
    int bh = blockIdx.y, b = bh >> 4, h = bh & 15;
    int q0 = blockIdx.x * AQ;
    size_t gbase = (size_t)(b * SEQ) * NQKV + h * DKH;

    const __nv_bfloat16* qh = qkvh;
    const __nv_bfloat16* ql = qkvl;
    const __nv_bfloat16* kh = qkvh + DMODEL;
    const __nv_bfloat16* kl = qkvl + DMODEL;
    const __nv_bfloat16* vh = qkvh + 2 * DMODEL;
    const __nv_bfloat16* vl = qkvl + 2 * DMODEL;

    // Load Q tile (hi+lo)
#pragma unroll
    for (int j = 0; j < 4; j++) {
        int e = tid + j * 256;
        int row = e >> 3, ch = e & 7;
        size_t g = gbase + (size_t)(q0 + row) * NQKV + ch * 8;
        cp_async16(sb + A_QH + row * ASTR + ch * 16, qh + g);
        cp_async16(sb + A_QL + row * ASTR + ch * 16, ql + g);
    }
    load_kv_tile(kh, kl, vh, vl, gbase, 0, sb + A_ST);
    cp_commit();

    const int ntiles = q0 / ATK + 2;

    float Sv[32], Oa[32];
#pragma unroll
    for (int i = 0; i < 32; i++) Oa[i] = 0.f;
    float m0 = -1e30f, m1 = -1e30f, l0 = 0.f, l1 = 0.f;

    int arow = (lane & 7) + ((lane >> 3) & 1) * 8;
    int akof = (lane >> 4) * 16;
    int brow = (lane & 7) + (lane >> 4) * 8;
    int bkof = ((lane >> 3) & 1) * 16;
    int vrow = (lane & 7) + ((lane >> 3) & 1) * 8;
    int vbyt = (lane >> 4) * 16;

    int wq = q0 + (wid << 4);
    int qrow0 = wq + (lane >> 2);

    for (int jt = 0; jt < ntiles; jt++) {
        int s = jt & 1;
        if (jt + 1 < ntiles) {
            load_kv_tile(kh, kl, vh, vl, gbase, (jt + 1) * ATK,
                         sb + A_ST + (s ^ 1) * A_STG);
            cp_commit();
            cp_wait<1>();
        } else {
            cp_wait<0>();
        }
        __syncthreads();

        int k0 = jt * ATK;
        if (k0 <= wq + 15) {
            uint32_t stk = sb + A_ST + s * A_STG;
#pragma unroll
            for (int i = 0; i < 32; i++) Sv[i] = 0.f;
            // --- scores: Q x K^T (split-3) ---
#pragma unroll
            for (int ks = 0; ks < 4; ks++) {
                uint32_t qfh[4], qfl[4];
                uint32_t qaddr = sb + A_QH + (wid * 16 + arow) * ASTR + ks * 32 + akof;
                ldmx4(qfh, qaddr);
                ldmx4(qfl, qaddr + A_QL);
#pragma unroll
                for (int g = 0; g < 4; g++) {
                    uint32_t kfh[4], kfl[4];
                    uint32_t kaddr = stk + (g * 16 + brow) * ASTR + ks * 32 + bkof;
                    ldmx4(kfh, kaddr);
                    ldmx4(kfl, kaddr + A_KL);
                    mma16816(&Sv[(g * 2) * 4],     qfh, &kfh[0]);
                    mma16816(&Sv[(g * 2) * 4],     qfl, &kfh[0]);
                    mma16816(&Sv[(g * 2) * 4],     qfh, &kfl[0]);
                    mma16816(&Sv[(g * 2 + 1) * 4], qfh, &kfh[2]);
                    mma16816(&Sv[(g * 2 + 1) * 4], qfl, &kfh[2]);
                    mma16816(&Sv[(g * 2 + 1) * 4], qfh, &kfl[2]);
                }
            }
            // --- scale + causal mask ---
            int keyb = k0 + ((lane & 3) << 1);
#pragma unroll
            for (int j = 0; j < 8; j++) {
                int key = keyb + j * 8;
                float s0 = Sv[j * 4 + 0] * 0.125f; if (key     > qrow0)     s0 = -1e9f;
                float s1 = Sv[j * 4 + 1] * 0.125f; if (key + 1 > qrow0)     s1 = -1e9f;
                float s2 = Sv[j * 4 + 2] * 0.125f; if (key     > qrow0 + 8) s2 = -1e9f;
                float s3 = Sv[j * 4 + 3] * 0.125f; if (key + 1 > qrow0 + 8) s3 = -1e9f;
                Sv[j * 4 + 0] = s0; Sv[j * 4 + 1] = s1;
                Sv[j * 4 + 2] = s2; Sv[j * 4 + 3] = s3;
            }
            // --- online softmax ---
            float mt0 = -1e30f, mt1 = -1e30f;
#pragma unroll
            for (int j = 0; j < 8; j++) {
                mt0 = fmaxf(mt0, fmaxf(Sv[j * 4 + 0], Sv[j * 4 + 1]));
                mt1 = fmaxf(mt1, fmaxf(Sv[j * 4 + 2], Sv[j * 4 + 3]));
            }
            mt0 = fmaxf(mt0, __shfl_xor_sync(0xffffffffu, mt0, 1));
            mt0 = fmaxf(mt0, __shfl_xor_sync(0xffffffffu, mt0, 2));
            mt1 = fmaxf(mt1, __shfl_xor_sync(0xffffffffu, mt1, 1));
            mt1 = fmaxf(mt1, __shfl_xor_sync(0xffffffffu, mt1, 2));
            float mn0 = fmaxf(m0, mt0), mn1 = fmaxf(m1, mt1);
            float c0 = __expf(m0 - mn0), c1 = __expf(m1 - mn1);
            l0 *= c0; l1 *= c1;
#pragma unroll
            for (int j = 0; j < 8; j++) {
                Oa[j * 4 + 0] *= c0; Oa[j * 4 + 1] *= c0;
                Oa[j * 4 + 2] *= c1; Oa[j * 4 + 3] *= c1;
            }
            float sum0 = 0.f, sum1 = 0.f;
#pragma unroll
            for (int j = 0; j < 8; j++) {
                float p0 = __expf(Sv[j * 4 + 0] - mn0);
                float p1 = __expf(Sv[j * 4 + 1] - mn0);
                float p2 = __expf(Sv[j * 4 + 2] - mn1);
                float p3 = __expf(Sv[j * 4 + 3] - mn1);
                Sv[j * 4 + 0] = p0; Sv[j * 4 + 1] = p1;
                Sv[j * 4 + 2] = p2; Sv[j * 4 + 3] = p3;
                sum0 += p0 + p1; sum1 += p2 + p3;
            }
            sum0 += __shfl_xor_sync(0xffffffffu, sum0, 1);
            sum0 += __shfl_xor_sync(0xffffffffu, sum0, 2);
            sum1 += __shfl_xor_sync(0xffffffffu, sum1, 1);
            sum1 += __shfl_xor_sync(0xffffffffu, sum1, 2);
            l0 += sum0; l1 += sum1;
            m0 = mn0; m1 = mn1;
            // --- P x V (split-3) ---
#pragma unroll
            for (int ks = 0; ks < 4; ks++) {
                uint32_t ph[4], pl[4];
                split_pair(Sv[8 * ks + 0], Sv[8 * ks + 1], ph[0], pl[0]);
                split_pair(Sv[8 * ks + 2], Sv[8 * ks + 3], ph[1], pl[1]);
                split_pair(Sv[8 * ks + 4], Sv[8 * ks + 5], ph[2], pl[2]);
                split_pair(Sv[8 * ks + 6], Sv[8 * ks + 7], ph[3], pl[3]);
#pragma unroll
                for (int nt = 0; nt < 4; nt++) {
                    uint32_t vfh[4], vfl[4];
                    uint32_t vaddr = stk + A_VH + (ks * 16 + vrow) * ASTR + nt * 32 + vbyt;
                    ldmx4t(vfh, vaddr);
                    ldmx4t(vfl, vaddr + (A_VL - A_VH));
                    mma16816(&Oa[(nt * 2) * 4],     ph, &vfh[0]);
                    mma16816(&Oa[(nt * 2) * 4],     pl, &vfh[0]);
                    mma16816(&Oa[(nt * 2) * 4],     ph, &vfl[0]);
                    mma16816(&Oa[(nt * 2 + 1) * 4], ph, &vfh[2]);
                    mma16816(&Oa[(nt * 2 + 1) * 4], pl, &vfh[2]);
                    mma16816(&Oa[(nt * 2 + 1) * 4], ph, &vfl[2]);
                }
            }
        }
        __syncthreads();
    }

    // Epilogue: normalize + split-bf16 store (output stride DMODEL)
    float inv0 = 1.f / l0, inv1 = 1.f / l1;
    size_t obase = (size_t)(b * SEQ) * DMODEL + h * DKH;
    size_t r0 = obase + (size_t)qrow0 * DMODEL;
    size_t r1 = obase + (size_t)(qrow0 + 8) * DMODEL;
#pragma unroll
    for (int nt = 0; nt < 8; nt++) {
        int col = nt * 8 + (lane & 3) * 2;
        uint32_t hi, lo;
        split_pair(Oa[nt * 4 + 0] * inv0, Oa[nt * 4 + 1] * inv0, hi, lo);
        *(uint32_t*)(Oh + r0 + col) = hi;
        *(uint32_t*)(Ol + r0 + col) = lo;
        split_pair(Oa[nt * 4 + 2] * inv1, Oa[nt * 4 + 3] * inv1, hi, lo);
        *(uint32_t*)(Oh + r1 + col) = hi;
        *(uint32_t*)(Ol + r1 + col) = lo;
    }
}

// ===========================================================================
// Launcher
// ===========================================================================
extern "C" void kernel_launch(void* const* d_in, const int* in_sizes, int n_in,
                              void* d_out, int out_size)
{
    const float* x   = (const float*)d_in[0];
    const float* Wq  = (const float*)d_in[2];
    const float* bq  = (const float*)d_in[3];
    const float* Wk  = (const float*)d_in[4];
    const float* bk  = (const float*)d_in[5];
    const float* Wv  = (const float*)d_in[6];
    const float* bv  = (const float*)d_in[7];
    const float* Wo  = (const float*)d_in[8];
    const float* bo  = (const float*)d_in[9];
    const float* W1  = (const float*)d_in[10];
    const float* b1  = (const float*)d_in[11];
    const float* W2  = (const float*)d_in[12];
    const float* b2  = (const float*)d_in[13];
    const float* g1  = (const float*)d_in[14];
    const float* be1 = (const float*)d_in[15];
    const float* g2  = (const float*)d_in[16];
    const float* be2 = (const float*)d_in[17];
    float* out = (float*)d_out;

    __nv_bfloat16 *xnh, *xnl, *ath, *atl, *ffh, *ffl, *qkvh, *qkvl;
    __nv_bfloat16 *wcath, *wcatl, *w1h, *w1l, *w2h, *w2l;
    float *h, *bqkv;
    cudaGetSymbolAddress((void**)&xnh, g_xnh); cudaGetSymbolAddress((void**)&xnl, g_xnl);
    cudaGetSymbolAddress((void**)&ath, g_ath); cudaGetSymbolAddress((void**)&atl, g_atl);
    cudaGetSymbolAddress((void**)&ffh, g_ffh); cudaGetSymbolAddress((void**)&ffl, g_ffl);
    cudaGetSymbolAddress((void**)&qkvh, g_qkvh); cudaGetSymbolAddress((void**)&qkvl, g_qkvl);
    cudaGetSymbolAddress((void**)&wcath, g_wcath); cudaGetSymbolAddress((void**)&wcatl, g_wcatl);
    cudaGetSymbolAddress((void**)&w1h, g_w1h); cudaGetSymbolAddress((void**)&w1l, g_w1l);
    cudaGetSymbolAddress((void**)&w2h, g_w2h); cudaGetSymbolAddress((void**)&w2l, g_w2l);
    cudaGetSymbolAddress((void**)&h, g_h);
    cudaGetSymbolAddress((void**)&bqkv, g_bqkv);

    __nv_bfloat16* woh = wcath + (size_t)3 * DMODEL * DMODEL;
    __nv_bfloat16* wol = wcatl + (size_t)3 * DMODEL * DMODEL;

    cudaFuncSetAttribute(gemm_hmma_kernel,
                         cudaFuncAttributeMaxDynamicSharedMemorySize, HSMEM_TOTAL);
    cudaFuncSetAttribute(flash_hmma_kernel,
                         cudaFuncAttributeMaxDynamicSharedMemorySize, ATT_SMEM);

    dim3 tb(256);
    // 1. bias concat
    concat_bias_kernel<<<NQKV / 256, 256>>>(bq, bk, bv, bqkv);
    // 2. batched transpose of Wq,Wk,Wv,Wo -> [WqT|WkT|WvT|WoT]
    transpose_split4_kernel<<<dim3(32, 32, 4), tb>>>(Wq, Wk, Wv, Wo, wcath, wcatl);
    // 3-4. FFN weight transposes
    transpose_split_kernel<<<dim3(DFF / 32, DMODEL / 32), tb>>>(W1, w1h, w1l, DMODEL, DFF);
    transpose_split_kernel<<<dim3(DMODEL / 32, DFF / 32), tb>>>(W2, w2h, w2l, DFF, DMODEL);
    // 5. LN1 -> split
    ln_kernel<<<NROWS, 256>>>(x, g1, be1, xnh, xnl);
    // 6. Fused QKV projection -> split-bf16 (mode 3)   [profiled launch]
    dim3 gQKV(NQKV / 128, NROWS / 128);
    gemm_hmma_kernel<<<gQKV, 256, HSMEM_TOTAL>>>(xnh, xnl, wcath, wcatl, bqkv, nullptr,
                                                 nullptr, qkvh, qkvl, NQKV, DMODEL, 3);
    // 7. Causal flash attention (HMMA) -> split
    dim3 gA(SEQ / AQ, BATCH * NHEAD);
    flash_hmma_kernel<<<gA, 256, ATT_SMEM>>>(qkvh, qkvl, ath, atl);
    // 8. Output projection + residual(x) -> h
    dim3 gO(DMODEL / 128, NROWS / 128);
    gemm_hmma_kernel<<<gO, 256, HSMEM_TOTAL>>>(ath, atl, woh, wol, bo, x, h,
                                               nullptr, nullptr, DMODEL, DMODEL, 1);
    // 9. LN2 -> split
    ln_kernel<<<NROWS, 256>>>(h, g2, be2, xnh, xnl);
    // 10. FFN1 + relu -> split
    dim3 gF1(DFF / 128, NROWS / 128);
    gemm_hmma_kernel<<<gF1, 256, HSMEM_TOTAL>>>(xnh, xnl, w1h, w1l, b1, nullptr,
                                                nullptr, ffh, ffl, DFF, DMODEL, 2);
    // 11. FFN2 + residual(h) -> out
    dim3 gF2(DMODEL / 128, NROWS / 128);
    gemm_hmma_kernel<<<gF2, 256, HSMEM_TOTAL>>>(ffh, ffl, w2h, w2l, b2, h, out,
                                                nullptr, nullptr, DMODEL, DFF, 1);
}

// round 6
// speedup vs baseline: 6.8506x; 2.4380x over previous
#include <cuda_runtime.h>
#include <cuda_fp16.h>
#include <cstdint>
#include <math.h>

// Problem constants
#define BATCH   2
#define SEQ     2048
#define DMODEL  1024
#define NHEAD   16
#define DKH     64
#define DFF     4096
#define NROWS   (BATCH * SEQ)   // 4096
#define NQKV    3072            // fused QKV output width

// ===========================================================================
// Helpers
// ===========================================================================
__device__ __forceinline__ uint32_t smem_to_u32(const void* p) {
    uint32_t a;
    asm("{ .reg .u64 t; cvta.to.shared.u64 t, %1; cvt.u32.u64 %0, t; }" : "=r"(a) : "l"(p));
    return a;
}
__device__ __forceinline__ void cp_async16(uint32_t s, const void* g) {
    asm volatile("cp.async.cg.shared.global [%0], [%1], 16;" :: "r"(s), "l"(g));
}
__device__ __forceinline__ void cp_commit() {
    asm volatile("cp.async.commit_group;" ::: "memory");
}
template <int N>
__device__ __forceinline__ void cp_wait() {
    asm volatile("cp.async.wait_group %0;" :: "n"(N) : "memory");
}
__device__ __forceinline__ void ldmx4(uint32_t* r, uint32_t addr) {
    asm volatile("ldmatrix.sync.aligned.m8n8.x4.shared.b16 {%0,%1,%2,%3}, [%4];"
                 : "=r"(r[0]), "=r"(r[1]), "=r"(r[2]), "=r"(r[3]) : "r"(addr));
}
__device__ __forceinline__ void ldmx4t(uint32_t* r, uint32_t addr) {
    asm volatile("ldmatrix.sync.aligned.m8n8.x4.trans.shared.b16 {%0,%1,%2,%3}, [%4];"
                 : "=r"(r[0]), "=r"(r[1]), "=r"(r[2]), "=r"(r[3]) : "r"(addr));
}
__device__ __forceinline__ void mma16816(float* d, const uint32_t* a, const uint32_t* b) {
    asm volatile("mma.sync.aligned.m16n8k16.row.col.f32.f16.f16.f32 "
                 "{%0,%1,%2,%3}, {%4,%5,%6,%7}, {%8,%9}, {%0,%1,%2,%3};"
                 : "+f"(d[0]), "+f"(d[1]), "+f"(d[2]), "+f"(d[3])
                 : "r"(a[0]), "r"(a[1]), "r"(a[2]), "r"(a[3]), "r"(b[0]), "r"(b[1]));
}
__device__ __forceinline__ uint32_t pack2h(float a, float b) {
    __half2 h = __floats2half2_rn(a, b);
    return *reinterpret_cast<uint32_t*>(&h);
}

// ===========================================================================
// Scratch (__device__ globals; no cudaMalloc allowed)
// ===========================================================================
__device__ __half g_xn [NROWS * DMODEL];
__device__ __half g_at [NROWS * DMODEL];
__device__ __half g_ff [NROWS * DFF];
__device__ __half g_qkv[NROWS * NQKV];
// 4 square weights transposed, contiguous: [WqT | WkT | WvT | WoT]
__device__ __half g_wcat[4 * DMODEL * DMODEL];
__device__ __half g_w1t[DFF * DMODEL];
__device__ __half g_w2t[DMODEL * DFF];
__device__ float g_bqkv[NQKV];
__device__ float g_h[NROWS * DMODEL];

// ===========================================================================
// Bias concat: [bq | bk | bv]
// ===========================================================================
__global__ void concat_bias_kernel(const float* __restrict__ bq,
                                   const float* __restrict__ bk,
                                   const float* __restrict__ bv,
                                   float* __restrict__ o)
{
    int i = blockIdx.x * blockDim.x + threadIdx.x;
    if (i < 1024)      o[i] = bq[i];
    else if (i < 2048) o[i] = bk[i - 1024];
    else               o[i] = bv[i - 2048];
}

// ===========================================================================
// Weight transpose + fp16 convert: W[K,N] fp32 -> T[N,K] fp16
// ===========================================================================
__global__ __launch_bounds__(256) void transpose_h_kernel(
    const float* __restrict__ W, __half* __restrict__ T, int K, int N)
{
    __shared__ float tile[32][33];
    int n0 = blockIdx.x * 32, k0 = blockIdx.y * 32;
    int tx = threadIdx.x & 31, ty = threadIdx.x >> 5;
#pragma unroll
    for (int i = 0; i < 4; i++)
        tile[ty + i * 8][tx] = W[(size_t)(k0 + ty + i * 8) * N + n0 + tx];
    __syncthreads();
#pragma unroll
    for (int i = 0; i < 4; i++) {
        size_t o = (size_t)(n0 + ty + i * 8) * K + k0 + tx;
        T[o] = __float2half_rn(tile[tx][ty + i * 8]);
    }
}

// Batched version for the four 1024x1024 weights.
__global__ __launch_bounds__(256) void transpose_h4_kernel(
    const float* __restrict__ W0, const float* __restrict__ W1x,
    const float* __restrict__ W2x, const float* __restrict__ W3x,
    __half* __restrict__ T)
{
    __shared__ float tile[32][33];
    int z = blockIdx.z;
    const float* W = (z == 0) ? W0 : (z == 1) ? W1x : (z == 2) ? W2x : W3x;
    size_t zoff = (size_t)z * DMODEL * DMODEL;
    int n0 = blockIdx.x * 32, k0 = blockIdx.y * 32;
    int tx = threadIdx.x & 31, ty = threadIdx.x >> 5;
#pragma unroll
    for (int i = 0; i < 4; i++)
        tile[ty + i * 8][tx] = W[(size_t)(k0 + ty + i * 8) * DMODEL + n0 + tx];
    __syncthreads();
#pragma unroll
    for (int i = 0; i < 4; i++) {
        size_t o = zoff + (size_t)(n0 + ty + i * 8) * DMODEL + k0 + tx;
        T[o] = __float2half_rn(tile[tx][ty + i * 8]);
    }
}

// ===========================================================================
// LayerNorm (fp16 output)
// ===========================================================================
__global__ __launch_bounds__(256) void ln_kernel(
    const float* __restrict__ X, const float* __restrict__ gamma,
    const float* __restrict__ beta, __half* __restrict__ Y)
{
    int row = blockIdx.x;
    int t   = threadIdx.x;
    float4 xv = ((const float4*)(X + (size_t)row * DMODEL))[t];
    float s = xv.x + xv.y + xv.z + xv.w;
    float q = xv.x * xv.x + xv.y * xv.y + xv.z * xv.z + xv.w * xv.w;
#pragma unroll
    for (int off = 16; off > 0; off >>= 1) {
        s += __shfl_xor_sync(0xffffffffu, s, off);
        q += __shfl_xor_sync(0xffffffffu, q, off);
    }
    __shared__ float ss[8], sq[8];
    if ((t & 31) == 0) { ss[t >> 5] = s; sq[t >> 5] = q; }
    __syncthreads();
    __shared__ float smu, srstd;
    if (t == 0) {
        float S = 0.f, Q = 0.f;
#pragma unroll
        for (int i = 0; i < 8; i++) { S += ss[i]; Q += sq[i]; }
        float mu  = S * (1.0f / DMODEL);
        float var = Q * (1.0f / DMODEL) - mu * mu;
        smu = mu; srstd = rsqrtf(var + 1e-5f);
    }
    __syncthreads();
    float mu = smu, r = srstd;
    float4 g4 = ((const float4*)gamma)[t];
    float4 b4 = ((const float4*)beta)[t];
    uint32_t p0 = pack2h((xv.x - mu) * r * g4.x + b4.x, (xv.y - mu) * r * g4.y + b4.y);
    uint32_t p1 = pack2h((xv.z - mu) * r * g4.z + b4.z, (xv.w - mu) * r * g4.w + b4.w);
    size_t base = (size_t)row * DMODEL + t * 4;
    *(uint32_t*)(Y + base)     = p0;
    *(uint32_t*)(Y + base + 2) = p1;
}

// ===========================================================================
// HMMA fp16 GEMM: C[M,N] = A @ Bt^T + bias. 128x128 CTA tile, 8 warps,
// warp tile 64x32, K chunk 64, 2-stage cp.async double buffer, 2 CTAs/SM.
// modes: 0 fp32+bias | 1 fp32+bias+res | 2 fp16+bias+relu | 3 fp16+bias
// ===========================================================================
#define BKC 64
#define TSTRIDE 144                    // 64 fp16 = 128B + 16B pad
#define TBYTES (128 * TSTRIDE)         // 18432
#define STG_BYTES (2 * TBYTES)         // 36864: A, B
#define HSMEM_TOTAL (2 * STG_BYTES)    // 73728

__device__ __forceinline__ void load_stage(
    const __half* __restrict__ A, const __half* __restrict__ B,
    int m0, int n0, int k0, int K, uint32_t sbase)
{
    int tid = threadIdx.x;
    const __half* gt[2] = { A + (size_t)m0 * K, B + (size_t)n0 * K };
#pragma unroll
    for (int T = 0; T < 2; T++) {
#pragma unroll
        for (int j = 0; j < 4; j++) {
            int e = tid + j * 256;          // 0..1023
            int row = e >> 3, s = e & 7;
            const void* g = (const char*)(gt[T] + (size_t)row * K + k0) + s * 16;
            cp_async16(sbase + T * TBYTES + row * TSTRIDE + s * 16, g);
        }
    }
}

__global__ __launch_bounds__(256, 2) void gemm_hmma_kernel(
    const __half* __restrict__ A, const __half* __restrict__ B,
    const float* __restrict__ bias, const float* __restrict__ res,
    float* __restrict__ outF, __half* __restrict__ outH,
    int N, int K, int mode)
{
    extern __shared__ char smem[];
    uint32_t sb = smem_to_u32(smem);
    int tid = threadIdx.x, wid = tid >> 5, lane = tid & 31;
    int m0 = blockIdx.y * 128, n0 = blockIdx.x * 128;
    int wy = wid >> 2, wx = wid & 3;

    float acc[4][4][4];
#pragma unroll
    for (int a = 0; a < 4; a++)
#pragma unroll
        for (int b = 0; b < 4; b++)
#pragma unroll
            for (int c = 0; c < 4; c++) acc[a][b][c] = 0.f;

    const int NC = K >> 6;

    load_stage(A, B, m0, n0, 0, K, sb);
    cp_commit();

    int arow = (lane & 7) + ((lane >> 3) & 1) * 8;
    int akof = (lane >> 4) * 16;
    int brow = (lane & 7) + (lane >> 4) * 8;
    int bkof = ((lane >> 3) & 1) * 16;

    for (int i = 0; i < NC; i++) {
        int s = i & 1;
        if (i + 1 < NC) {
            load_stage(A, B, m0, n0, (i + 1) * BKC, K, sb + (s ^ 1) * STG_BYTES);
            cp_commit();
            cp_wait<1>();
        } else {
            cp_wait<0>();
        }
        __syncthreads();

        uint32_t st = sb + s * STG_BYTES;
#pragma unroll
        for (int kh = 0; kh < 4; kh++) {
            uint32_t Af[4][4];
            uint32_t Bf[4][2];
#pragma unroll
            for (int mt = 0; mt < 4; mt++) {
                uint32_t addr = st + (wy * 64 + mt * 16 + arow) * TSTRIDE + kh * 32 + akof;
                ldmx4(Af[mt], addr);
            }
#pragma unroll
            for (int ntp = 0; ntp < 2; ntp++) {
                uint32_t addr = st + TBYTES +
                                (wx * 32 + ntp * 16 + brow) * TSTRIDE + kh * 32 + bkof;
                uint32_t r[4];
                ldmx4(r, addr);
                Bf[ntp * 2][0] = r[0]; Bf[ntp * 2][1] = r[1];
                Bf[ntp * 2 + 1][0] = r[2]; Bf[ntp * 2 + 1][1] = r[3];
            }
#pragma unroll
            for (int mt = 0; mt < 4; mt++)
#pragma unroll
                for (int nt = 0; nt < 4; nt++)
                    mma16816(acc[mt][nt], Af[mt], Bf[nt]);
        }
        __syncthreads();
    }

#pragma unroll
    for (int mt = 0; mt < 4; mt++) {
#pragma unroll
        for (int nt = 0; nt < 4; nt++) {
            int r0 = m0 + wy * 64 + mt * 16 + (lane >> 2);
            int c  = n0 + wx * 32 + nt * 8 + (lane & 3) * 2;
            float b0 = bias[c], b1 = bias[c + 1];
#pragma unroll
            for (int half = 0; half < 2; half++) {
                int r = r0 + half * 8;
                float v0 = acc[mt][nt][half * 2 + 0] + b0;
                float v1 = acc[mt][nt][half * 2 + 1] + b1;
                size_t o = (size_t)r * N + c;
                if (mode >= 2) {
                    if (mode == 2) { v0 = fmaxf(v0, 0.f); v1 = fmaxf(v1, 0.f); }
                    *(uint32_t*)(outH + o) = pack2h(v0, v1);
                } else {
                    if (mode == 1) {
                        float2 rr = *(const float2*)(res + o);
                        v0 += rr.x; v1 += rr.y;
                    }
                    float2 w; w.x = v0; w.y = v1;
                    *(float2*)(outF + o) = w;
                }
            }
        }
    }
}

// ===========================================================================
// HMMA fp16 flash attention (causal), reads fused QKV (stride 3072).
// Block: 256 threads (8 warps), 128 q-rows (16/warp), KV tiles of 64.
// ===========================================================================
#define AQ 128
#define ATK 64
#define ASTR 144
#define A_Q 0
#define A_ST (128 * ASTR)                     // 18432
#define A_STG (2 * 64 * ASTR)                 // 18432 per stage (K + V)
#define A_V (64 * ASTR)
#define ATT_SMEM (A_ST + 2 * A_STG)           // 55296

__device__ __forceinline__ void load_kv_tile(
    const __half* __restrict__ kp, const __half* __restrict__ vp,
    size_t gbase, int k0, uint32_t sbase)
{
    int tid = threadIdx.x;
#pragma unroll
    for (int j = 0; j < 2; j++) {
        int e = tid + j * 256;
        int row = e >> 3, ch = e & 7;
        size_t g = gbase + (size_t)(k0 + row) * NQKV + ch * 8;
        uint32_t so = row * ASTR + ch * 16;
        cp_async16(sbase + so,       kp + g);
        cp_async16(sbase + A_V + so, vp + g);
    }
}

__global__ __launch_bounds__(256, 1) void flash_hmma_kernel(
    const __half* __restrict__ qkv, __half* __restrict__ O)
{
    extern __shared__ char smem[];
    uint32_t sb = smem_to_u32(smem);
    int tid = threadIdx.x, wid = tid >> 5, lane = tid & 31;
    int bh = blockIdx.y, b = bh >> 4, h = bh & 15;
    int q0 = blockIdx.x * AQ;
    size_t gbase = (size_t)(b * SEQ) * NQKV + h * DKH;

    const __half* qp = qkv;
    const __half* kp = qkv + DMODEL;
    const __half* vp = qkv + 2 * DMODEL;

    // Load Q tile
#pragma unroll
    for (int j = 0; j < 4; j++) {
        int e = tid + j * 256;
        int row = e >> 3, ch = e & 7;
        size_t g = gbase + (size_t)(q0 + row) * NQKV + ch * 8;
        cp_async16(sb + A_Q + row * ASTR + ch * 16, qp + g);
    }
    load_kv_tile(kp, vp, gbase, 0, sb + A_ST);
    cp_commit();

    const int ntiles = q0 / ATK + 2;

    float Sv[32], Oa[32];
#pragma unroll
    for (int i = 0; i < 32; i++) Oa[i] = 0.f;
    float m0 = -1e30f, m1 = -1e30f, l0 = 0.f, l1 = 0.f;

    int arow = (lane & 7) + ((lane >> 3) & 1) * 8;
    int akof = (lane >> 4) * 16;
    int brow = (lane & 7) + (lane >> 4) * 8;
    int bkof = ((lane >> 3) & 1) * 16;
    int vrow = (lane & 7) + ((lane >> 3) & 1) * 8;
    int vbyt = (lane >> 4) * 16;

    int wq = q0 + (wid << 4);
    int qrow0 = wq + (lane >> 2);

    for (int jt = 0; jt < ntiles; jt++) {
        int s = jt & 1;
        if (jt + 1 < ntiles) {
            load_kv_tile(kp, vp, gbase, (jt + 1) * ATK, sb + A_ST + (s ^ 1) * A_STG);
            cp_commit();
            cp_wait<1>();
        } else {
            cp_wait<0>();
        }
        __syncthreads();

        int k0 = jt * ATK;
        if (k0 <= wq + 15) {
            uint32_t stk = sb + A_ST + s * A_STG;
#pragma unroll
            for (int i = 0; i < 32; i++) Sv[i] = 0.f;
            // --- scores: Q x K^T ---
#pragma unroll
            for (int ks = 0; ks < 4; ks++) {
                uint32_t qf[4];
                uint32_t qaddr = sb + A_Q + (wid * 16 + arow) * ASTR + ks * 32 + akof;
                ldmx4(qf, qaddr);
#pragma unroll
                for (int g = 0; g < 4; g++) {
                    uint32_t kf[4];
                    uint32_t kaddr = stk + (g * 16 + brow) * ASTR + ks * 32 + bkof;
                    ldmx4(kf, kaddr);
                    mma16816(&Sv[(g * 2) * 4],     qf, &kf[0]);
                    mma16816(&Sv[(g * 2 + 1) * 4], qf, &kf[2]);
                }
            }
            // --- scale + causal mask ---
            int keyb = k0 + ((lane & 3) << 1);
#pragma unroll
            for (int j = 0; j < 8; j++) {
                int key = keyb + j * 8;
                float s0 = Sv[j * 4 + 0] * 0.125f; if (key     > qrow0)     s0 = -1e9f;
                float s1 = Sv[j * 4 + 1] * 0.125f; if (key + 1 > qrow0)     s1 = -1e9f;
                float s2 = Sv[j * 4 + 2] * 0.125f; if (key     > qrow0 + 8) s2 = -1e9f;
                float s3 = Sv[j * 4 + 3] * 0.125f; if (key + 1 > qrow0 + 8) s3 = -1e9f;
                Sv[j * 4 + 0] = s0; Sv[j * 4 + 1] = s1;
                Sv[j * 4 + 2] = s2; Sv[j * 4 + 3] = s3;
            }
            // --- online softmax ---
            float mt0 = -1e30f, mt1 = -1e30f;
#pragma unroll
            for (int j = 0; j < 8; j++) {
                mt0 = fmaxf(mt0, fmaxf(Sv[j * 4 + 0], Sv[j * 4 + 1]));
                mt1 = fmaxf(mt1, fmaxf(Sv[j * 4 + 2], Sv[j * 4 + 3]));
            }
            mt0 = fmaxf(mt0, __shfl_xor_sync(0xffffffffu, mt0, 1));
            mt0 = fmaxf(mt0, __shfl_xor_sync(0xffffffffu, mt0, 2));
            mt1 = fmaxf(mt1, __shfl_xor_sync(0xffffffffu, mt1, 1));
            mt1 = fmaxf(mt1, __shfl_xor_sync(0xffffffffu, mt1, 2));
            float mn0 = fmaxf(m0, mt0), mn1 = fmaxf(m1, mt1);
            float c0 = __expf(m0 - mn0), c1 = __expf(m1 - mn1);
            l0 *= c0; l1 *= c1;
#pragma unroll
            for (int j = 0; j < 8; j++) {
                Oa[j * 4 + 0] *= c0; Oa[j * 4 + 1] *= c0;
                Oa[j * 4 + 2] *= c1; Oa[j * 4 + 3] *= c1;
            }
            float sum0 = 0.f, sum1 = 0.f;
#pragma unroll
            for (int j = 0; j < 8; j++) {
                float p0 = __expf(Sv[j * 4 + 0] - mn0);
                float p1 = __expf(Sv[j * 4 + 1] - mn0);
                float p2 = __expf(Sv[j * 4 + 2] - mn1);
                float p3 = __expf(Sv[j * 4 + 3] - mn1);
                Sv[j * 4 + 0] = p0; Sv[j * 4 + 1] = p1;
                Sv[j * 4 + 2] = p2; Sv[j * 4 + 3] = p3;
                sum0 += p0 + p1; sum1 += p2 + p3;
            }
            sum0 += __shfl_xor_sync(0xffffffffu, sum0, 1);
            sum0 += __shfl_xor_sync(0xffffffffu, sum0, 2);
            sum1 += __shfl_xor_sync(0xffffffffu, sum1, 1);
            sum1 += __shfl_xor_sync(0xffffffffu, sum1, 2);
            l0 += sum0; l1 += sum1;
            m0 = mn0; m1 = mn1;
            // --- P x V ---
#pragma unroll
            for (int ks = 0; ks < 4; ks++) {
                uint32_t pf[4];
                pf[0] = pack2h(Sv[8 * ks + 0], Sv[8 * ks + 1]);
                pf[1] = pack2h(Sv[8 * ks + 2], Sv[8 * ks + 3]);
                pf[2] = pack2h(Sv[8 * ks + 4], Sv[8 * ks + 5]);
                pf[3] = pack2h(Sv[8 * ks + 6], Sv[8 * ks + 7]);
#pragma unroll
                for (int nt = 0; nt < 4; nt++) {
                    uint32_t vf[4];
                    uint32_t vaddr = stk + A_V + (ks * 16 + vrow) * ASTR + nt * 32 + vbyt;
                    ldmx4t(vf, vaddr);
                    mma16816(&Oa[(nt * 2) * 4],     pf, &vf[0]);
                    mma16816(&Oa[(nt * 2 + 1) * 4], pf, &vf[2]);
                }
            }
        }
        __syncthreads();
    }

    // Epilogue: normalize + fp16 store (output stride DMODEL)
    float inv0 = 1.f / l0, inv1 = 1.f / l1;
    size_t obase = (size_t)(b * SEQ) * DMODEL + h * DKH;
    size_t r0 = obase + (size_t)qrow0 * DMODEL;
    size_t r1 = obase + (size_t)(qrow0 + 8) * DMODEL;
#pragma unroll
    for (int nt = 0; nt < 8; nt++) {
        int col = nt * 8 + (lane & 3) * 2;
        *(uint32_t*)(O + r0 + col) = pack2h(Oa[nt * 4 + 0] * inv0, Oa[nt * 4 + 1] * inv0);
        *(uint32_t*)(O + r1 + col) = pack2h(Oa[nt * 4 + 2] * inv1, Oa[nt * 4 + 3] * inv1);
    }
}

// ===========================================================================
// Launcher
// ===========================================================================
extern "C" void kernel_launch(void* const* d_in, const int* in_sizes, int n_in,
                              void* d_out, int out_size)
{
    const float* x   = (const float*)d_in[0];
    const float* Wq  = (const float*)d_in[2];
    const float* bq  = (const float*)d_in[3];
    const float* Wk  = (const float*)d_in[4];
    const float* bk  = (const float*)d_in[5];
    const float* Wv  = (const float*)d_in[6];
    const float* bv  = (const float*)d_in[7];
    const float* Wo  = (const float*)d_in[8];
    const float* bo  = (const float*)d_in[9];
    const float* W1  = (const float*)d_in[10];
    const float* b1  = (const float*)d_in[11];
    const float* W2  = (const float*)d_in[12];
    const float* b2  = (const float*)d_in[13];
    const float* g1  = (const float*)d_in[14];
    const float* be1 = (const float*)d_in[15];
    const float* g2  = (const float*)d_in[16];
    const float* be2 = (const float*)d_in[17];
    float* out = (float*)d_out;

    __half *xn, *at, *ff, *qkv, *wcat, *w1t, *w2t;
    float *h, *bqkv;
    cudaGetSymbolAddress((void**)&xn, g_xn);
    cudaGetSymbolAddress((void**)&at, g_at);
    cudaGetSymbolAddress((void**)&ff, g_ff);
    cudaGetSymbolAddress((void**)&qkv, g_qkv);
    cudaGetSymbolAddress((void**)&wcat, g_wcat);
    cudaGetSymbolAddress((void**)&w1t, g_w1t);
    cudaGetSymbolAddress((void**)&w2t, g_w2t);
    cudaGetSymbolAddress((void**)&h, g_h);
    cudaGetSymbolAddress((void**)&bqkv, g_bqkv);

    __half* wot = wcat + (size_t)3 * DMODEL * DMODEL;

    cudaFuncSetAttribute(gemm_hmma_kernel,
                         cudaFuncAttributeMaxDynamicSharedMemorySize, HSMEM_TOTAL);
    cudaFuncSetAttribute(flash_hmma_kernel,
                         cudaFuncAttributeMaxDynamicSharedMemorySize, ATT_SMEM);

    dim3 tb(256);
    // 1. bias concat
    concat_bias_kernel<<<NQKV / 256, 256>>>(bq, bk, bv, bqkv);
    // 2. batched transpose of Wq,Wk,Wv,Wo -> [WqT|WkT|WvT|WoT]
    transpose_h4_kernel<<<dim3(32, 32, 4), tb>>>(Wq, Wk, Wv, Wo, wcat);
    // 3-4. FFN weight transposes
    transpose_h_kernel<<<dim3(DFF / 32, DMODEL / 32), tb>>>(W1, w1t, DMODEL, DFF);
    transpose_h_kernel<<<dim3(DMODEL / 32, DFF / 32), tb>>>(W2, w2t, DFF, DMODEL);
    // 5. LN1 -> fp16
    ln_kernel<<<NROWS, 256>>>(x, g1, be1, xn);
    // 6. Fused QKV projection -> fp16 (mode 3)   [profiled launch]
    dim3 gQKV(NQKV / 128, NROWS / 128);
    gemm_hmma_kernel<<<gQKV, 256, HSMEM_TOTAL>>>(xn, wcat, bqkv, nullptr,
                                                 nullptr, qkv, NQKV, DMODEL, 3);
    // 7. Causal flash attention (HMMA) -> fp16
    dim3 gA(SEQ / AQ, BATCH * NHEAD);
    flash_hmma_kernel<<<gA, 256, ATT_SMEM>>>(qkv, at);
    // 8. Output projection + residual(x) -> h (fp32)
    dim3 gO(DMODEL / 128, NROWS / 128);
    gemm_hmma_kernel<<<gO, 256, HSMEM_TOTAL>>>(at, wot, bo, x, h,
                                               nullptr, DMODEL, DMODEL, 1);
    // 9. LN2 -> fp16
    ln_kernel<<<NROWS, 256>>>(h, g2, be2, xn);
    // 10. FFN1 + relu -> fp16
    dim3 gF1(DFF / 128, NROWS / 128);
    gemm_hmma_kernel<<<gF1, 256, HSMEM_TOTAL>>>(xn, w1t, b1, nullptr,
                                                nullptr, ff, DFF, DMODEL, 2);
    // 11. FFN2 + residual(h) -> out (fp32)
    dim3 gF2(DMODEL / 128, NROWS / 128);
    gemm_hmma_kernel<<<gF2, 256, HSMEM_TOTAL>>>(ff, w2t, b2, h, out,
                                                nullptr, DMODEL, DFF, 1);
}